// round 1
// baseline (speedup 1.0000x reference)
#include <cuda_runtime.h>
#include <math_constants.h>

#define EMBED  1024
#define HEADS  16
#define HDIM   64
#define HIDDEN 4096
#define SEQ    2048
#define BATCH  2
#define NTOK   (BATCH*SEQ)

// ---------------- scratch (static device globals; no runtime alloc) ----------
__device__ float g_q[NTOK * EMBED];
__device__ float g_k[NTOK * EMBED];
__device__ float g_v[NTOK * EMBED];
__device__ float g_ctx[NTOK * EMBED];
__device__ float g_tmp[NTOK * EMBED];
__device__ float g_x1[NTOK * EMBED];
__device__ float g_h1[(size_t)NTOK * HIDDEN];
__device__ float g_scores[(size_t)BATCH * HEADS * SEQ * SEQ];   // 512 MB

// ---------------- generic tiled SGEMM --------------------------------------
// C[M,N] = alpha * A(M,K) x B  (+bias) (+relu), batched via blockIdx.z with
// offset = (z/inner)*outerStride + (z%inner)*innerStride per operand.
// TRANS_B=false: B is [K,N] row-major (ldb = row stride)
// TRANS_B=true : B is [N,K] row-major (C = A * B^T)
// Requires: M % BM == 0, N % BN == 0, K % BK == 0 (all shapes here comply).
template<int BM, int BN, int BK, int TM, int TN, bool TRANS_B, bool RELU>
__global__ void __launch_bounds__((BM/TM)*(BN/TN))
gemm_kernel(const float* __restrict__ A, int lda, long long aOut, long long aIn,
            const float* __restrict__ B, int ldb, long long bOut, long long bIn,
            float* __restrict__ C, int ldc, long long cOut, long long cIn,
            const float* __restrict__ bias,
            int M, int N, int K, float alpha, int inner)
{
    constexpr int THREADS = (BM/TM)*(BN/TN);
    const int z  = blockIdx.z;
    const int ob = z / inner;
    const int oi = z - ob * inner;
    A += (long long)ob * aOut + (long long)oi * aIn;
    B += (long long)ob * bOut + (long long)oi * bIn;
    C += (long long)ob * cOut + (long long)oi * cIn;

    __shared__ float As[BK][BM];
    __shared__ float Bs[BK][BN];

    const int tid = threadIdx.x;
    const int tx  = tid % (BN/TN);
    const int ty  = tid / (BN/TN);
    const int rowBase = blockIdx.y * BM;
    const int colBase = blockIdx.x * BN;

    float acc[TM][TN];
#pragma unroll
    for (int i = 0; i < TM; i++)
#pragma unroll
        for (int j = 0; j < TN; j++) acc[i][j] = 0.f;

    for (int k0 = 0; k0 < K; k0 += BK) {
        // load A tile: BM x BK
#pragma unroll
        for (int i = 0; i < (BM*BK)/THREADS; i++) {
            int idx = i * THREADS + tid;
            int r  = idx / BK;
            int kk = idx % BK;
            As[kk][r] = A[(long long)(rowBase + r) * lda + (k0 + kk)];
        }
        // load B tile: BK x BN
        if (!TRANS_B) {
#pragma unroll
            for (int i = 0; i < (BK*BN)/THREADS; i++) {
                int idx = i * THREADS + tid;
                int kk = idx / BN;
                int c  = idx % BN;
                Bs[kk][c] = B[(long long)(k0 + kk) * ldb + (colBase + c)];
            }
        } else {
#pragma unroll
            for (int i = 0; i < (BK*BN)/THREADS; i++) {
                int idx = i * THREADS + tid;
                int c  = idx / BK;
                int kk = idx % BK;
                Bs[kk][c] = B[(long long)(colBase + c) * ldb + (k0 + kk)];
            }
        }
        __syncthreads();

#pragma unroll
        for (int kk = 0; kk < BK; kk++) {
            float ra[TM], rb[TN];
#pragma unroll
            for (int i = 0; i < TM; i++) ra[i] = As[kk][ty*TM + i];
#pragma unroll
            for (int j = 0; j < TN; j++) rb[j] = Bs[kk][tx*TN + j];
#pragma unroll
            for (int i = 0; i < TM; i++)
#pragma unroll
                for (int j = 0; j < TN; j++)
                    acc[i][j] += ra[i] * rb[j];
        }
        __syncthreads();
    }

#pragma unroll
    for (int i = 0; i < TM; i++) {
        int r = rowBase + ty*TM + i;
#pragma unroll
        for (int j = 0; j < TN; j++) {
            int c = colBase + tx*TN + j;
            float vv = acc[i][j] * alpha;
            if (bias) vv += bias[c];
            if (RELU) vv = fmaxf(vv, 0.f);
            C[(long long)r * ldc + c] = vv;
        }
    }
}

// ---------------- row softmax over SEQ=2048 (one block per row) -------------
__global__ void __launch_bounds__(256) softmax_rows(float* __restrict__ S)
{
    float* row = S + (size_t)blockIdx.x * SEQ;
    const int tid = threadIdx.x;

    float4 v0 = reinterpret_cast<float4*>(row)[tid];
    float4 v1 = reinterpret_cast<float4*>(row)[tid + 256];

    float m = fmaxf(fmaxf(fmaxf(v0.x, v0.y), fmaxf(v0.z, v0.w)),
                    fmaxf(fmaxf(v1.x, v1.y), fmaxf(v1.z, v1.w)));

    __shared__ float red[8];
#pragma unroll
    for (int o = 16; o > 0; o >>= 1)
        m = fmaxf(m, __shfl_xor_sync(0xffffffffu, m, o));
    const int wid = tid >> 5, lane = tid & 31;
    if (lane == 0) red[wid] = m;
    __syncthreads();
    m = red[0];
#pragma unroll
    for (int w = 1; w < 8; w++) m = fmaxf(m, red[w]);
    __syncthreads();

    v0.x = __expf(v0.x - m); v0.y = __expf(v0.y - m);
    v0.z = __expf(v0.z - m); v0.w = __expf(v0.w - m);
    v1.x = __expf(v1.x - m); v1.y = __expf(v1.y - m);
    v1.z = __expf(v1.z - m); v1.w = __expf(v1.w - m);

    float s = v0.x + v0.y + v0.z + v0.w + v1.x + v1.y + v1.z + v1.w;
#pragma unroll
    for (int o = 16; o > 0; o >>= 1)
        s += __shfl_xor_sync(0xffffffffu, s, o);
    if (lane == 0) red[wid] = s;
    __syncthreads();
    s = red[0];
#pragma unroll
    for (int w = 1; w < 8; w++) s += red[w];

    const float inv = 1.f / s;
    v0.x *= inv; v0.y *= inv; v0.z *= inv; v0.w *= inv;
    v1.x *= inv; v1.y *= inv; v1.z *= inv; v1.w *= inv;

    reinterpret_cast<float4*>(row)[tid]       = v0;
    reinterpret_cast<float4*>(row)[tid + 256] = v1;
}

// ---------------- residual add + LayerNorm over EMBED=1024 ------------------
__global__ void __launch_bounds__(256)
add_layernorm(const float* __restrict__ X, const float* __restrict__ Y,
              const float* __restrict__ gamma, const float* __restrict__ beta,
              float* __restrict__ O)
{
    const size_t base = (size_t)blockIdx.x * EMBED;
    const int tid = threadIdx.x;

    float4 xv = reinterpret_cast<const float4*>(X + base)[tid];
    float4 yv = reinterpret_cast<const float4*>(Y + base)[tid];
    float4 r;
    r.x = xv.x + yv.x; r.y = xv.y + yv.y;
    r.z = xv.z + yv.z; r.w = xv.w + yv.w;

    float s  = r.x + r.y + r.z + r.w;
    float sq = r.x*r.x + r.y*r.y + r.z*r.z + r.w*r.w;

    __shared__ float rs[8];
    __shared__ float rq[8];
#pragma unroll
    for (int o = 16; o > 0; o >>= 1) {
        s  += __shfl_xor_sync(0xffffffffu, s,  o);
        sq += __shfl_xor_sync(0xffffffffu, sq, o);
    }
    const int wid = tid >> 5, lane = tid & 31;
    if (lane == 0) { rs[wid] = s; rq[wid] = sq; }
    __syncthreads();
    s = rs[0]; sq = rq[0];
#pragma unroll
    for (int w = 1; w < 8; w++) { s += rs[w]; sq += rq[w]; }

    const float mu   = s * (1.f / EMBED);
    const float var  = sq * (1.f / EMBED) - mu * mu;
    const float rstd = rsqrtf(var + 1e-6f);

    float4 g = reinterpret_cast<const float4*>(gamma)[tid];
    float4 b = reinterpret_cast<const float4*>(beta)[tid];
    float4 o;
    o.x = (r.x - mu) * rstd * g.x + b.x;
    o.y = (r.y - mu) * rstd * g.y + b.y;
    o.z = (r.z - mu) * rstd * g.z + b.z;
    o.w = (r.w - mu) * rstd * g.w + b.w;
    reinterpret_cast<float4*>(O + base)[tid] = o;
}

// ---------------- host launch ------------------------------------------------
extern "C" void kernel_launch(void* const* d_in, const int* in_sizes, int n_in,
                              void* d_out, int out_size)
{
    const float* x     = (const float*)d_in[0];
    const float* Wq    = (const float*)d_in[1];
    const float* bq    = (const float*)d_in[2];
    const float* Wk    = (const float*)d_in[3];
    const float* bk    = (const float*)d_in[4];
    const float* Wv    = (const float*)d_in[5];
    const float* bv    = (const float*)d_in[6];
    const float* Wo    = (const float*)d_in[7];
    const float* bo    = (const float*)d_in[8];
    const float* ln1_g = (const float*)d_in[9];
    const float* ln1_b = (const float*)d_in[10];
    const float* W1    = (const float*)d_in[11];
    const float* b1    = (const float*)d_in[12];
    const float* W2    = (const float*)d_in[13];
    const float* b2    = (const float*)d_in[14];
    const float* ln2_g = (const float*)d_in[15];
    const float* ln2_b = (const float*)d_in[16];
    float* out = (float*)d_out;

    float *q, *k, *v, *ctx, *scores, *tmp, *x1, *h1;
    cudaGetSymbolAddress((void**)&q,      g_q);
    cudaGetSymbolAddress((void**)&k,      g_k);
    cudaGetSymbolAddress((void**)&v,      g_v);
    cudaGetSymbolAddress((void**)&ctx,    g_ctx);
    cudaGetSymbolAddress((void**)&scores, g_scores);
    cudaGetSymbolAddress((void**)&tmp,    g_tmp);
    cudaGetSymbolAddress((void**)&x1,     g_x1);
    cudaGetSymbolAddress((void**)&h1,     g_h1);

    const long long SO = (long long)SEQ * EMBED;        // per-batch stride in q/k/v/ctx
    const long long SS = (long long)SEQ * SEQ;          // per-(b,h) stride in scores

    // --- QKV projections: [4096,1024] x [1024,1024] + bias
    dim3 gP(EMBED/128, NTOK/128, 1);
    gemm_kernel<128,128,8,8,8,false,false><<<gP, 256>>>(
        x, EMBED, 0, 0,  Wq, EMBED, 0, 0,  q, EMBED, 0, 0,
        bq, NTOK, EMBED, EMBED, 1.f, 1);
    gemm_kernel<128,128,8,8,8,false,false><<<gP, 256>>>(
        x, EMBED, 0, 0,  Wk, EMBED, 0, 0,  k, EMBED, 0, 0,
        bk, NTOK, EMBED, EMBED, 1.f, 1);
    gemm_kernel<128,128,8,8,8,false,false><<<gP, 256>>>(
        x, EMBED, 0, 0,  Wv, EMBED, 0, 0,  v, EMBED, 0, 0,
        bv, NTOK, EMBED, EMBED, 1.f, 1);

    // --- scores[b,h] = (Q_h K_h^T) / 8 : batched NT, M=N=2048, K=64
    dim3 gS(SEQ/128, SEQ/128, BATCH*HEADS);
    gemm_kernel<128,128,8,8,8,true,false><<<gS, 256>>>(
        q, EMBED, SO, HDIM,   k, EMBED, SO, HDIM,
        scores, SEQ, (long long)HEADS*SS, SS,
        nullptr, SEQ, SEQ, HDIM, 0.125f, HEADS);

    // --- softmax over last dim
    softmax_rows<<<BATCH*HEADS*SEQ, 256>>>(scores);

    // --- ctx[b,h] = attn @ V_h : batched NN, M=2048, N=64, K=2048
    dim3 gC(HDIM/64, SEQ/128, BATCH*HEADS);
    gemm_kernel<128,64,8,8,4,false,false><<<gC, 256>>>(
        scores, SEQ, (long long)HEADS*SS, SS,
        v, EMBED, SO, HDIM,
        ctx, EMBED, SO, HDIM,
        nullptr, SEQ, HDIM, SEQ, 1.f, HEADS);

    // --- attn_out = ctx @ Wo + bo
    gemm_kernel<128,128,8,8,8,false,false><<<gP, 256>>>(
        ctx, EMBED, 0, 0,  Wo, EMBED, 0, 0,  tmp, EMBED, 0, 0,
        bo, NTOK, EMBED, EMBED, 1.f, 1);

    // --- x1 = LN(x + attn_out)
    add_layernorm<<<NTOK, 256>>>(x, tmp, ln1_g, ln1_b, x1);

    // --- h1 = relu(x1 @ W1 + b1) : [4096,1024]x[1024,4096]
    dim3 gF1(HIDDEN/128, NTOK/128, 1);
    gemm_kernel<128,128,8,8,8,false,true><<<gF1, 256>>>(
        x1, EMBED, 0, 0,  W1, HIDDEN, 0, 0,  h1, HIDDEN, 0, 0,
        b1, NTOK, HIDDEN, EMBED, 1.f, 1);

    // --- f2 = h1 @ W2 + b2 : [4096,4096]x[4096,1024]
    gemm_kernel<128,128,8,8,8,false,false><<<gP, 256>>>(
        h1, HIDDEN, 0, 0,  W2, EMBED, 0, 0,  tmp, EMBED, 0, 0,
        b2, NTOK, EMBED, HIDDEN, 1.f, 1);

    // --- out = LN(x1 + f2)
    add_layernorm<<<NTOK, 256>>>(x1, tmp, ln2_g, ln2_b, out);
}

// round 2
// speedup vs baseline: 1.0021x; 1.0021x over previous
#include <cuda_runtime.h>
#include <math_constants.h>

#define EMBED  1024
#define HEADS  16
#define HDIM   64
#define HIDDEN 4096
#define SEQ    2048
#define BATCH  2
#define NTOK   (BATCH*SEQ)

// ---------------- scratch (static device globals; no runtime alloc) ----------
__device__ float g_q[NTOK * EMBED];
__device__ float g_k[NTOK * EMBED];
__device__ float g_v[NTOK * EMBED];
__device__ float g_ctx[NTOK * EMBED];
__device__ float g_tmp[NTOK * EMBED];
__device__ float g_x1[NTOK * EMBED];
__device__ float g_h1[(size_t)NTOK * HIDDEN];
__device__ float g_scores[(size_t)BATCH * HEADS * SEQ * SEQ];   // 512 MB

// ---------------- generic tiled SGEMM --------------------------------------
// C[M,N] = alpha * A(M,K) x B  (+bias) (+relu), batched via blockIdx.z with
// offset = (z/inner)*outerStride + (z%inner)*innerStride per operand.
// TRANS_B=false: B is [K,N] row-major (ldb = row stride)
// TRANS_B=true : B is [N,K] row-major (C = A * B^T)
// Requires: M % BM == 0, N % BN == 0, K % BK == 0 (all shapes here comply).
template<int BM, int BN, int BK, int TM, int TN, bool TRANS_B, bool RELU>
__global__ void __launch_bounds__((BM/TM)*(BN/TN))
gemm_kernel(const float* __restrict__ A, int lda, long long aOut, long long aIn,
            const float* __restrict__ B, int ldb, long long bOut, long long bIn,
            float* __restrict__ C, int ldc, long long cOut, long long cIn,
            const float* __restrict__ bias,
            int M, int N, int K, float alpha, int inner)
{
    constexpr int THREADS = (BM/TM)*(BN/TN);
    const int z  = blockIdx.z;
    const int ob = z / inner;
    const int oi = z - ob * inner;
    A += (long long)ob * aOut + (long long)oi * aIn;
    B += (long long)ob * bOut + (long long)oi * bIn;
    C += (long long)ob * cOut + (long long)oi * cIn;

    __shared__ float As[BK][BM];
    __shared__ float Bs[BK][BN];

    const int tid = threadIdx.x;
    const int tx  = tid % (BN/TN);
    const int ty  = tid / (BN/TN);
    const int rowBase = blockIdx.y * BM;
    const int colBase = blockIdx.x * BN;

    float acc[TM][TN];
#pragma unroll
    for (int i = 0; i < TM; i++)
#pragma unroll
        for (int j = 0; j < TN; j++) acc[i][j] = 0.f;

    for (int k0 = 0; k0 < K; k0 += BK) {
        // load A tile: BM x BK
#pragma unroll
        for (int i = 0; i < (BM*BK)/THREADS; i++) {
            int idx = i * THREADS + tid;
            int r  = idx / BK;
            int kk = idx % BK;
            As[kk][r] = A[(long long)(rowBase + r) * lda + (k0 + kk)];
        }
        // load B tile: BK x BN
        if (!TRANS_B) {
#pragma unroll
            for (int i = 0; i < (BK*BN)/THREADS; i++) {
                int idx = i * THREADS + tid;
                int kk = idx / BN;
                int c  = idx % BN;
                Bs[kk][c] = B[(long long)(k0 + kk) * ldb + (colBase + c)];
            }
        } else {
#pragma unroll
            for (int i = 0; i < (BK*BN)/THREADS; i++) {
                int idx = i * THREADS + tid;
                int c  = idx / BK;
                int kk = idx % BK;
                Bs[kk][c] = B[(long long)(colBase + c) * ldb + (k0 + kk)];
            }
        }
        __syncthreads();

#pragma unroll
        for (int kk = 0; kk < BK; kk++) {
            float ra[TM], rb[TN];
#pragma unroll
            for (int i = 0; i < TM; i++) ra[i] = As[kk][ty*TM + i];
#pragma unroll
            for (int j = 0; j < TN; j++) rb[j] = Bs[kk][tx*TN + j];
#pragma unroll
            for (int i = 0; i < TM; i++)
#pragma unroll
                for (int j = 0; j < TN; j++)
                    acc[i][j] += ra[i] * rb[j];
        }
        __syncthreads();
    }

#pragma unroll
    for (int i = 0; i < TM; i++) {
        int r = rowBase + ty*TM + i;
#pragma unroll
        for (int j = 0; j < TN; j++) {
            int c = colBase + tx*TN + j;
            float vv = acc[i][j] * alpha;
            if (bias) vv += bias[c];
            if (RELU) vv = fmaxf(vv, 0.f);
            C[(long long)r * ldc + c] = vv;
        }
    }
}

// ---------------- row softmax over SEQ=2048 (one block per row) -------------
__global__ void __launch_bounds__(256) softmax_rows(float* __restrict__ S)
{
    float* row = S + (size_t)blockIdx.x * SEQ;
    const int tid = threadIdx.x;

    float4 v0 = reinterpret_cast<float4*>(row)[tid];
    float4 v1 = reinterpret_cast<float4*>(row)[tid + 256];

    float m = fmaxf(fmaxf(fmaxf(v0.x, v0.y), fmaxf(v0.z, v0.w)),
                    fmaxf(fmaxf(v1.x, v1.y), fmaxf(v1.z, v1.w)));

    __shared__ float red[8];
#pragma unroll
    for (int o = 16; o > 0; o >>= 1)
        m = fmaxf(m, __shfl_xor_sync(0xffffffffu, m, o));
    const int wid = tid >> 5, lane = tid & 31;
    if (lane == 0) red[wid] = m;
    __syncthreads();
    m = red[0];
#pragma unroll
    for (int w = 1; w < 8; w++) m = fmaxf(m, red[w]);
    __syncthreads();

    v0.x = __expf(v0.x - m); v0.y = __expf(v0.y - m);
    v0.z = __expf(v0.z - m); v0.w = __expf(v0.w - m);
    v1.x = __expf(v1.x - m); v1.y = __expf(v1.y - m);
    v1.z = __expf(v1.z - m); v1.w = __expf(v1.w - m);

    float s = v0.x + v0.y + v0.z + v0.w + v1.x + v1.y + v1.z + v1.w;
#pragma unroll
    for (int o = 16; o > 0; o >>= 1)
        s += __shfl_xor_sync(0xffffffffu, s, o);
    if (lane == 0) red[wid] = s;
    __syncthreads();
    s = red[0];
#pragma unroll
    for (int w = 1; w < 8; w++) s += red[w];

    const float inv = 1.f / s;
    v0.x *= inv; v0.y *= inv; v0.z *= inv; v0.w *= inv;
    v1.x *= inv; v1.y *= inv; v1.z *= inv; v1.w *= inv;

    reinterpret_cast<float4*>(row)[tid]       = v0;
    reinterpret_cast<float4*>(row)[tid + 256] = v1;
}

// ---------------- residual add + LayerNorm over EMBED=1024 ------------------
__global__ void __launch_bounds__(256)
add_layernorm(const float* __restrict__ X, const float* __restrict__ Y,
              const float* __restrict__ gamma, const float* __restrict__ beta,
              float* __restrict__ O)
{
    const size_t base = (size_t)blockIdx.x * EMBED;
    const int tid = threadIdx.x;

    float4 xv = reinterpret_cast<const float4*>(X + base)[tid];
    float4 yv = reinterpret_cast<const float4*>(Y + base)[tid];
    float4 r;
    r.x = xv.x + yv.x; r.y = xv.y + yv.y;
    r.z = xv.z + yv.z; r.w = xv.w + yv.w;

    float s  = r.x + r.y + r.z + r.w;
    float sq = r.x*r.x + r.y*r.y + r.z*r.z + r.w*r.w;

    __shared__ float rs[8];
    __shared__ float rq[8];
#pragma unroll
    for (int o = 16; o > 0; o >>= 1) {
        s  += __shfl_xor_sync(0xffffffffu, s,  o);
        sq += __shfl_xor_sync(0xffffffffu, sq, o);
    }
    const int wid = tid >> 5, lane = tid & 31;
    if (lane == 0) { rs[wid] = s; rq[wid] = sq; }
    __syncthreads();
    s = rs[0]; sq = rq[0];
#pragma unroll
    for (int w = 1; w < 8; w++) { s += rs[w]; sq += rq[w]; }

    const float mu   = s * (1.f / EMBED);
    const float var  = sq * (1.f / EMBED) - mu * mu;
    const float rstd = rsqrtf(var + 1e-6f);

    float4 g = reinterpret_cast<const float4*>(gamma)[tid];
    float4 b = reinterpret_cast<const float4*>(beta)[tid];
    float4 o;
    o.x = (r.x - mu) * rstd * g.x + b.x;
    o.y = (r.y - mu) * rstd * g.y + b.y;
    o.z = (r.z - mu) * rstd * g.z + b.z;
    o.w = (r.w - mu) * rstd * g.w + b.w;
    reinterpret_cast<float4*>(O + base)[tid] = o;
}

// ---------------- host launch ------------------------------------------------
extern "C" void kernel_launch(void* const* d_in, const int* in_sizes, int n_in,
                              void* d_out, int out_size)
{
    const float* x     = (const float*)d_in[0];
    const float* Wq    = (const float*)d_in[1];
    const float* bq    = (const float*)d_in[2];
    const float* Wk    = (const float*)d_in[3];
    const float* bk    = (const float*)d_in[4];
    const float* Wv    = (const float*)d_in[5];
    const float* bv    = (const float*)d_in[6];
    const float* Wo    = (const float*)d_in[7];
    const float* bo    = (const float*)d_in[8];
    const float* ln1_g = (const float*)d_in[9];
    const float* ln1_b = (const float*)d_in[10];
    const float* W1    = (const float*)d_in[11];
    const float* b1    = (const float*)d_in[12];
    const float* W2    = (const float*)d_in[13];
    const float* b2    = (const float*)d_in[14];
    const float* ln2_g = (const float*)d_in[15];
    const float* ln2_b = (const float*)d_in[16];
    float* out = (float*)d_out;

    float *q, *k, *v, *ctx, *scores, *tmp, *x1, *h1;
    cudaGetSymbolAddress((void**)&q,      g_q);
    cudaGetSymbolAddress((void**)&k,      g_k);
    cudaGetSymbolAddress((void**)&v,      g_v);
    cudaGetSymbolAddress((void**)&ctx,    g_ctx);
    cudaGetSymbolAddress((void**)&scores, g_scores);
    cudaGetSymbolAddress((void**)&tmp,    g_tmp);
    cudaGetSymbolAddress((void**)&x1,     g_x1);
    cudaGetSymbolAddress((void**)&h1,     g_h1);

    const long long SO = (long long)SEQ * EMBED;        // per-batch stride in q/k/v/ctx
    const long long SS = (long long)SEQ * SEQ;          // per-(b,h) stride in scores

    // --- QKV projections: [4096,1024] x [1024,1024] + bias
    dim3 gP(EMBED/128, NTOK/128, 1);
    gemm_kernel<128,128,8,8,8,false,false><<<gP, 256>>>(
        x, EMBED, 0, 0,  Wq, EMBED, 0, 0,  q, EMBED, 0, 0,
        bq, NTOK, EMBED, EMBED, 1.f, 1);
    gemm_kernel<128,128,8,8,8,false,false><<<gP, 256>>>(
        x, EMBED, 0, 0,  Wk, EMBED, 0, 0,  k, EMBED, 0, 0,
        bk, NTOK, EMBED, EMBED, 1.f, 1);
    gemm_kernel<128,128,8,8,8,false,false><<<gP, 256>>>(
        x, EMBED, 0, 0,  Wv, EMBED, 0, 0,  v, EMBED, 0, 0,
        bv, NTOK, EMBED, EMBED, 1.f, 1);

    // --- scores[b,h] = (Q_h K_h^T) / 8 : batched NT, M=N=2048, K=64
    dim3 gS(SEQ/128, SEQ/128, BATCH*HEADS);
    gemm_kernel<128,128,8,8,8,true,false><<<gS, 256>>>(
        q, EMBED, SO, HDIM,   k, EMBED, SO, HDIM,
        scores, SEQ, (long long)HEADS*SS, SS,
        nullptr, SEQ, SEQ, HDIM, 0.125f, HEADS);

    // --- softmax over last dim
    softmax_rows<<<BATCH*HEADS*SEQ, 256>>>(scores);

    // --- ctx[b,h] = attn @ V_h : batched NN, M=2048, N=64, K=2048
    dim3 gC(HDIM/64, SEQ/128, BATCH*HEADS);
    gemm_kernel<128,64,8,8,4,false,false><<<gC, 256>>>(
        scores, SEQ, (long long)HEADS*SS, SS,
        v, EMBED, SO, HDIM,
        ctx, EMBED, SO, HDIM,
        nullptr, SEQ, HDIM, SEQ, 1.f, HEADS);

    // --- attn_out = ctx @ Wo + bo
    gemm_kernel<128,128,8,8,8,false,false><<<gP, 256>>>(
        ctx, EMBED, 0, 0,  Wo, EMBED, 0, 0,  tmp, EMBED, 0, 0,
        bo, NTOK, EMBED, EMBED, 1.f, 1);

    // --- x1 = LN(x + attn_out)
    add_layernorm<<<NTOK, 256>>>(x, tmp, ln1_g, ln1_b, x1);

    // --- h1 = relu(x1 @ W1 + b1) : [4096,1024]x[1024,4096]
    dim3 gF1(HIDDEN/128, NTOK/128, 1);
    gemm_kernel<128,128,8,8,8,false,true><<<gF1, 256>>>(
        x1, EMBED, 0, 0,  W1, HIDDEN, 0, 0,  h1, HIDDEN, 0, 0,
        b1, NTOK, HIDDEN, EMBED, 1.f, 1);

    // --- f2 = h1 @ W2 + b2 : [4096,4096]x[4096,1024]
    gemm_kernel<128,128,8,8,8,false,false><<<gP, 256>>>(
        h1, HIDDEN, 0, 0,  W2, EMBED, 0, 0,  tmp, EMBED, 0, 0,
        b2, NTOK, EMBED, HIDDEN, 1.f, 1);

    // --- out = LN(x1 + f2)
    add_layernorm<<<NTOK, 256>>>(x1, tmp, ln2_g, ln2_b, out);
}

// round 4
// speedup vs baseline: 2.6268x; 2.6212x over previous
#include <cuda_runtime.h>
#include <cuda_bf16.h>
#include <cstdint>

#define EMBED  1024
#define HEADS  16
#define HDIM   64
#define HIDDEN 4096
#define SEQ    2048
#define BATCH  2
#define NTOK   (BATCH*SEQ)
#define NBH    (BATCH*HEADS)

typedef __nv_bfloat16 bf16;

// ---------------- static scratch --------------------------------------------
__device__ float g_scores[(size_t)NBH*SEQ*SEQ];
__device__ bf16  g_p_hi[(size_t)NBH*SEQ*SEQ];
__device__ bf16  g_p_lo[(size_t)NBH*SEQ*SEQ];
__device__ bf16  g_x_hi[NTOK*EMBED],  g_x_lo[NTOK*EMBED];
__device__ bf16  g_q_hi[NTOK*EMBED],  g_q_lo[NTOK*EMBED];
__device__ bf16  g_k_hi[NTOK*EMBED],  g_k_lo[NTOK*EMBED];
__device__ float g_v[NTOK*EMBED];
__device__ bf16  g_vt_hi[NTOK*EMBED], g_vt_lo[NTOK*EMBED];   // [b,h][64][2048]
__device__ bf16  g_c_hi[NTOK*EMBED],  g_c_lo[NTOK*EMBED];
__device__ float g_tmp[NTOK*EMBED];
__device__ float g_x1[NTOK*EMBED];
__device__ bf16  g_x1_hi[NTOK*EMBED], g_x1_lo[NTOK*EMBED];
__device__ bf16  g_h_hi[(size_t)NTOK*HIDDEN], g_h_lo[(size_t)NTOK*HIDDEN];
__device__ bf16  g_wT_hi[12*1024*1024], g_wT_lo[12*1024*1024];
#define OFF_WQ 0
#define OFF_WK (1*1024*1024)
#define OFF_WV (2*1024*1024)
#define OFF_WO (3*1024*1024)
#define OFF_W1 (4*1024*1024)
#define OFF_W2 (8*1024*1024)

// ---------------- helpers ----------------------------------------------------
__device__ __forceinline__ uint32_t smem_u32(const void* p) {
    uint32_t a;
    asm("{ .reg .u64 t; cvta.to.shared.u64 t, %1; cvt.u32.u64 %0, t; }" : "=r"(a) : "l"(p));
    return a;
}
__device__ __forceinline__ void cp16(const void* smem_dst, const void* gsrc) {
    uint32_t d = smem_u32(smem_dst);
    asm volatile("cp.async.cg.shared.global [%0], [%1], 16;" :: "r"(d), "l"(gsrc) : "memory");
}
#define CP_COMMIT() asm volatile("cp.async.commit_group;" ::: "memory")
#define CP_WAIT(n)  asm volatile("cp.async.wait_group %0;" :: "n"(n) : "memory")

__device__ __forceinline__ void mma16816(float* c, const uint32_t* a, const uint32_t* b) {
    asm volatile("mma.sync.aligned.m16n8k16.row.col.f32.bf16.bf16.f32 "
        "{%0,%1,%2,%3}, {%4,%5,%6,%7}, {%8,%9}, {%0,%1,%2,%3};"
        : "+f"(c[0]), "+f"(c[1]), "+f"(c[2]), "+f"(c[3])
        : "r"(a[0]), "r"(a[1]), "r"(a[2]), "r"(a[3]), "r"(b[0]), "r"(b[1]));
}
__device__ __forceinline__ void fsplit(float v, bf16& h, bf16& l) {
    h = __float2bfloat16_rn(v);
    l = __float2bfloat16_rn(v - __bfloat162float(h));
}
__device__ __forceinline__ uint32_t pack2(bf16 a, bf16 b) {
    __nv_bfloat162 t; t.x = a; t.y = b; return *(uint32_t*)&t;
}

// ---------------- bf16x3 HMMA GEMM -------------------------------------------
// D[M,N] = alpha * sum_k A[m,k]*B[n,k] (+bias)(+relu). A,B as hi/lo bf16 pairs.
// BM=128, BK=32, double-buffered cp.async. 256 threads = 8 warps.
// EPI: 0 = fp32 out, 1 = split bf16 out, 2 = relu + split bf16 out
template<int BN, int EPI>
__global__ void __launch_bounds__(256)
bgemm(const bf16* __restrict__ Ah, const bf16* __restrict__ Al, int lda,
      long long aOut, long long aIn,
      const bf16* __restrict__ Bh, const bf16* __restrict__ Bl, int ldb,
      long long bOut, long long bIn,
      float* Cf, bf16* Ch, bf16* Cl, int ldc, long long cOut, long long cIn,
      const float* __restrict__ bias, float alpha, int K, int inner)
{
    constexpr int BM = 128, BK = 32, BKP = 40;           // padded row stride (bf16)
    constexpr int WM = (BN == 128) ? 2 : 4, WN = 8 / WM; // warp grid
    constexpr int WTM = BM / WM, WTN = BN / WN;          // warp tile
    constexpr int MI = WTM / 16, NI = WTN / 8;
    constexpr int ASZ = BM * BKP;                        // elems per operand half
    constexpr int BSZ = BN * BKP;
    constexpr int SST = 2*ASZ + 2*BSZ;                   // elems per stage
    constexpr int CHA = BM * 4 * 2;                      // 16B chunks (A hi+lo)
    constexpr int CHB = BN * 4 * 2;
    constexpr int ITER = (CHA + CHB) / 256;

    extern __shared__ bf16 sm[];

    const int tid = threadIdx.x;
    const int warp = tid >> 5, lane = tid & 31;
    const int g = lane >> 2, t4 = lane & 3;
    const int wm = (warp % WM) * WTM;
    const int wn = (warp / WM) * WTN;

    const int z = blockIdx.z, ob = z / inner, oi = z - ob*inner;
    Ah += (long long)ob*aOut + (long long)oi*aIn;
    Al += (long long)ob*aOut + (long long)oi*aIn;
    Bh += (long long)ob*bOut + (long long)oi*bIn;
    Bl += (long long)ob*bOut + (long long)oi*bIn;
    const long long coff = (long long)ob*cOut + (long long)oi*cIn;
    if (EPI == 0) Cf += coff; else { Ch += coff; Cl += coff; }

    const int rowBase = blockIdx.y * BM;
    const int colBase = blockIdx.x * BN;

    float acc[MI][NI][4];
#pragma unroll
    for (int mi = 0; mi < MI; mi++)
#pragma unroll
        for (int ni = 0; ni < NI; ni++)
#pragma unroll
            for (int i = 0; i < 4; i++) acc[mi][ni][i] = 0.f;

    // ---- stage loader (cp.async, 16B chunks) --------------------------------
    auto load_stage = [&](int s, int k0) {
        bf16* st = sm + s * SST;
#pragma unroll
        for (int i = 0; i < ITER; i++) {
            int idx = i * 256 + tid;
            if (idx < CHA) {
                int half = idx >> 9;              // 512 chunks per half (BM*4)
                int r    = (idx >> 2) & (BM - 1);
                int c    = idx & 3;
                const bf16* src = (half ? Al : Ah) + (size_t)(rowBase + r)*lda + k0 + c*8;
                cp16(st + half*ASZ + r*BKP + c*8, src);
            } else {
                int j = idx - CHA;
                int half = j / (BN * 4);
                int r    = (j >> 2) % BN;
                int c    = j & 3;
                const bf16* src = (half ? Bl : Bh) + (size_t)(colBase + r)*ldb + k0 + c*8;
                cp16(st + 2*ASZ + half*BSZ + r*BKP + c*8, src);
            }
        }
    };

    const int T = K / BK;
    load_stage(0, 0);
    CP_COMMIT();

    for (int t = 0; t < T; t++) {
        if (t + 1 < T) {
            load_stage((t + 1) & 1, (t + 1) * BK);
            CP_COMMIT();
            CP_WAIT(1);
        } else {
            CP_WAIT(0);
        }
        __syncthreads();

        const bf16* sAh = sm + (t & 1) * SST;
        const bf16* sAl = sAh + ASZ;
        const bf16* sBh = sAl + ASZ;
        const bf16* sBl = sBh + BSZ;

#pragma unroll
        for (int kk = 0; kk < BK; kk += 16) {
            uint32_t ah[MI][4], al[MI][4];
#pragma unroll
            for (int mi = 0; mi < MI; mi++) {
                int r0 = wm + mi*16 + g;
                int c0 = kk + t4*2;
                ah[mi][0] = *(const uint32_t*)&sAh[(r0  )*BKP + c0    ];
                ah[mi][1] = *(const uint32_t*)&sAh[(r0+8)*BKP + c0    ];
                ah[mi][2] = *(const uint32_t*)&sAh[(r0  )*BKP + c0 + 8];
                ah[mi][3] = *(const uint32_t*)&sAh[(r0+8)*BKP + c0 + 8];
                al[mi][0] = *(const uint32_t*)&sAl[(r0  )*BKP + c0    ];
                al[mi][1] = *(const uint32_t*)&sAl[(r0+8)*BKP + c0    ];
                al[mi][2] = *(const uint32_t*)&sAl[(r0  )*BKP + c0 + 8];
                al[mi][3] = *(const uint32_t*)&sAl[(r0+8)*BKP + c0 + 8];
            }
            uint32_t bh[NI][2], bl[NI][2];
#pragma unroll
            for (int ni = 0; ni < NI; ni++) {
                int rn = wn + ni*8 + g;
                int ck = kk + t4*2;
                bh[ni][0] = *(const uint32_t*)&sBh[rn*BKP + ck    ];
                bh[ni][1] = *(const uint32_t*)&sBh[rn*BKP + ck + 8];
                bl[ni][0] = *(const uint32_t*)&sBl[rn*BKP + ck    ];
                bl[ni][1] = *(const uint32_t*)&sBl[rn*BKP + ck + 8];
            }
#pragma unroll
            for (int mi = 0; mi < MI; mi++)
#pragma unroll
                for (int ni = 0; ni < NI; ni++) {
                    mma16816(acc[mi][ni], ah[mi], bh[ni]);
                    mma16816(acc[mi][ni], ah[mi], bl[ni]);
                    mma16816(acc[mi][ni], al[mi], bh[ni]);
                }
        }
        __syncthreads();
    }

    // ---- epilogue: registers -> global --------------------------------------
#pragma unroll
    for (int ni = 0; ni < NI; ni++) {
        int col = colBase + wn + ni*8 + t4*2;
        float b0 = 0.f, b1 = 0.f;
        if (bias) { b0 = __ldg(bias + col); b1 = __ldg(bias + col + 1); }
#pragma unroll
        for (int mi = 0; mi < MI; mi++) {
            int row0 = rowBase + wm + mi*16 + g;
            float v0 = acc[mi][ni][0] * alpha + b0;
            float v1 = acc[mi][ni][1] * alpha + b1;
            float v2 = acc[mi][ni][2] * alpha + b0;
            float v3 = acc[mi][ni][3] * alpha + b1;
            if (EPI == 2) {
                v0 = fmaxf(v0, 0.f); v1 = fmaxf(v1, 0.f);
                v2 = fmaxf(v2, 0.f); v3 = fmaxf(v3, 0.f);
            }
            if (EPI == 0) {
                float2 r01; r01.x = v0; r01.y = v1;
                float2 r23; r23.x = v2; r23.y = v3;
                *(float2*)(Cf + (size_t)row0     * ldc + col) = r01;
                *(float2*)(Cf + (size_t)(row0+8) * ldc + col) = r23;
            } else {
                bf16 h0,l0,h1,l1,h2,l2,h3,l3;
                fsplit(v0,h0,l0); fsplit(v1,h1,l1);
                fsplit(v2,h2,l2); fsplit(v3,h3,l3);
                *(uint32_t*)(Ch + (size_t)row0     * ldc + col) = pack2(h0,h1);
                *(uint32_t*)(Cl + (size_t)row0     * ldc + col) = pack2(l0,l1);
                *(uint32_t*)(Ch + (size_t)(row0+8) * ldc + col) = pack2(h2,h3);
                *(uint32_t*)(Cl + (size_t)(row0+8) * ldc + col) = pack2(l2,l3);
            }
        }
    }
}

// ---------------- split fp32 -> hi/lo bf16 -----------------------------------
__global__ void __launch_bounds__(256) split_fp32(const float* __restrict__ in,
                                                  bf16* __restrict__ oh,
                                                  bf16* __restrict__ ol, int n4)
{
    int i = blockIdx.x*256 + threadIdx.x;
    if (i >= n4) return;
    float4 v = ((const float4*)in)[i];
    bf16 h[4], l[4];
    fsplit(v.x,h[0],l[0]); fsplit(v.y,h[1],l[1]);
    fsplit(v.z,h[2],l[2]); fsplit(v.w,h[3],l[3]);
    uint2 uh; uh.x = pack2(h[0],h[1]); uh.y = pack2(h[2],h[3]);
    uint2 ul; ul.x = pack2(l[0],l[1]); ul.y = pack2(l[2],l[3]);
    ((uint2*)oh)[i] = uh;
    ((uint2*)ol)[i] = ul;
}

// ---------------- batched transpose+split fp32[R,C] -> bf16 [C,R] ------------
__global__ void __launch_bounds__(256)
transpose_split(const float* __restrict__ in, long long inOuter, long long inInner,
                int innerB, int ldi,
                bf16* __restrict__ oh, bf16* __restrict__ ol,
                long long outStride, int ldo)
{
    __shared__ float tile[32][33];
    const int z = blockIdx.z;
    const float* src = in + (long long)(z/innerB)*inOuter + (long long)(z%innerB)*inInner;
    bf16* dh = oh + (long long)z*outStride;
    bf16* dl = ol + (long long)z*outStride;
    const int c0 = blockIdx.x*32, r0 = blockIdx.y*32;
    const int tx = threadIdx.x & 31, ty = threadIdx.x >> 5;
#pragma unroll
    for (int i = 0; i < 4; i++)
        tile[ty + i*8][tx] = src[(long long)(r0 + ty + i*8)*ldi + c0 + tx];
    __syncthreads();
#pragma unroll
    for (int i = 0; i < 4; i++) {
        bf16 h, l; fsplit(tile[tx][ty + i*8], h, l);
        long long o = (long long)(c0 + ty + i*8)*ldo + r0 + tx;
        dh[o] = h; dl[o] = l;
    }
}

// ---------------- softmax rows -> split bf16 ----------------------------------
__global__ void __launch_bounds__(256) softmax_split(const float* __restrict__ S,
                                                     bf16* __restrict__ Ph,
                                                     bf16* __restrict__ Pl)
{
    const size_t base = (size_t)blockIdx.x * SEQ;
    const int tid = threadIdx.x;
    float4 a = ((const float4*)(S + base))[2*tid];
    float4 b = ((const float4*)(S + base))[2*tid+1];

    float m = fmaxf(fmaxf(fmaxf(a.x,a.y),fmaxf(a.z,a.w)),
                    fmaxf(fmaxf(b.x,b.y),fmaxf(b.z,b.w)));
    __shared__ float red[8];
#pragma unroll
    for (int o = 16; o > 0; o >>= 1) m = fmaxf(m, __shfl_xor_sync(~0u, m, o));
    const int wid = tid>>5, lane = tid&31;
    if (lane == 0) red[wid] = m;
    __syncthreads();
    m = red[0];
#pragma unroll
    for (int w = 1; w < 8; w++) m = fmaxf(m, red[w]);
    __syncthreads();

    a.x=__expf(a.x-m); a.y=__expf(a.y-m); a.z=__expf(a.z-m); a.w=__expf(a.w-m);
    b.x=__expf(b.x-m); b.y=__expf(b.y-m); b.z=__expf(b.z-m); b.w=__expf(b.w-m);
    float s = a.x+a.y+a.z+a.w+b.x+b.y+b.z+b.w;
#pragma unroll
    for (int o = 16; o > 0; o >>= 1) s += __shfl_xor_sync(~0u, s, o);
    if (lane == 0) red[wid] = s;
    __syncthreads();
    s = red[0];
#pragma unroll
    for (int w = 1; w < 8; w++) s += red[w];
    const float inv = 1.f / s;

    float p[8] = {a.x*inv,a.y*inv,a.z*inv,a.w*inv,b.x*inv,b.y*inv,b.z*inv,b.w*inv};
    uint4 uh, ul;
    uint32_t* U = (uint32_t*)&uh; uint32_t* L = (uint32_t*)&ul;
#pragma unroll
    for (int i = 0; i < 4; i++) {
        bf16 h0,l0,h1,l1;
        fsplit(p[2*i],h0,l0); fsplit(p[2*i+1],h1,l1);
        U[i] = pack2(h0,h1); L[i] = pack2(l0,l1);
    }
    ((uint4*)(Ph + base))[tid] = uh;
    ((uint4*)(Pl + base))[tid] = ul;
}

// ---------------- residual + LayerNorm (optional split out) -------------------
template<bool SPLIT>
__global__ void __launch_bounds__(256)
add_ln(const float* __restrict__ X, const float* __restrict__ Y,
       const float* __restrict__ gamma, const float* __restrict__ beta,
       float* __restrict__ O, bf16* __restrict__ Oh, bf16* __restrict__ Ol)
{
    const size_t base = (size_t)blockIdx.x * EMBED;
    const int tid = threadIdx.x;
    float4 xv = ((const float4*)(X + base))[tid];
    float4 yv = ((const float4*)(Y + base))[tid];
    float4 r; r.x=xv.x+yv.x; r.y=xv.y+yv.y; r.z=xv.z+yv.z; r.w=xv.w+yv.w;

    float s = r.x+r.y+r.z+r.w;
    float sq = r.x*r.x+r.y*r.y+r.z*r.z+r.w*r.w;
    __shared__ float rs[8], rq[8];
#pragma unroll
    for (int o = 16; o > 0; o >>= 1) {
        s += __shfl_xor_sync(~0u, s, o);
        sq += __shfl_xor_sync(~0u, sq, o);
    }
    const int wid = tid>>5, lane = tid&31;
    if (lane == 0) { rs[wid]=s; rq[wid]=sq; }
    __syncthreads();
    s = rs[0]; sq = rq[0];
#pragma unroll
    for (int w = 1; w < 8; w++) { s += rs[w]; sq += rq[w]; }

    const float mu = s * (1.f/EMBED);
    const float var = sq * (1.f/EMBED) - mu*mu;
    const float rstd = rsqrtf(var + 1e-6f);
    float4 g = ((const float4*)gamma)[tid];
    float4 bb = ((const float4*)beta)[tid];
    float4 o;
    o.x=(r.x-mu)*rstd*g.x+bb.x; o.y=(r.y-mu)*rstd*g.y+bb.y;
    o.z=(r.z-mu)*rstd*g.z+bb.z; o.w=(r.w-mu)*rstd*g.w+bb.w;
    ((float4*)(O + base))[tid] = o;
    if (SPLIT) {
        bf16 h[4], l[4];
        fsplit(o.x,h[0],l[0]); fsplit(o.y,h[1],l[1]);
        fsplit(o.z,h[2],l[2]); fsplit(o.w,h[3],l[3]);
        uint2 uh; uh.x=pack2(h[0],h[1]); uh.y=pack2(h[2],h[3]);
        uint2 ul; ul.x=pack2(l[0],l[1]); ul.y=pack2(l[2],l[3]);
        ((uint2*)(Oh + base))[tid] = uh;
        ((uint2*)(Ol + base))[tid] = ul;
    }
}

// ---------------- host --------------------------------------------------------
extern "C" void kernel_launch(void* const* d_in, const int* in_sizes, int n_in,
                              void* d_out, int out_size)
{
    const float* x  = (const float*)d_in[0];
    const float* Wq = (const float*)d_in[1];  const float* bq = (const float*)d_in[2];
    const float* Wk = (const float*)d_in[3];  const float* bk = (const float*)d_in[4];
    const float* Wv = (const float*)d_in[5];  const float* bv = (const float*)d_in[6];
    const float* Wo = (const float*)d_in[7];  const float* bo = (const float*)d_in[8];
    const float* g1 = (const float*)d_in[9];  const float* be1 = (const float*)d_in[10];
    const float* W1 = (const float*)d_in[11]; const float* b1 = (const float*)d_in[12];
    const float* W2 = (const float*)d_in[13]; const float* b2 = (const float*)d_in[14];
    const float* g2 = (const float*)d_in[15]; const float* be2 = (const float*)d_in[16];
    float* out = (float*)d_out;

    float *scores, *v, *tmp, *x1;
    bf16 *ph,*pl,*xh,*xl,*qh,*ql,*kh,*kl,*vth,*vtl,*ch,*cl,*x1h,*x1l,*hh,*hl,*wth,*wtl;
    cudaGetSymbolAddress((void**)&scores, g_scores);
    cudaGetSymbolAddress((void**)&v,   g_v);
    cudaGetSymbolAddress((void**)&tmp, g_tmp);
    cudaGetSymbolAddress((void**)&x1,  g_x1);
    cudaGetSymbolAddress((void**)&ph,  g_p_hi);  cudaGetSymbolAddress((void**)&pl,  g_p_lo);
    cudaGetSymbolAddress((void**)&xh,  g_x_hi);  cudaGetSymbolAddress((void**)&xl,  g_x_lo);
    cudaGetSymbolAddress((void**)&qh,  g_q_hi);  cudaGetSymbolAddress((void**)&ql,  g_q_lo);
    cudaGetSymbolAddress((void**)&kh,  g_k_hi);  cudaGetSymbolAddress((void**)&kl,  g_k_lo);
    cudaGetSymbolAddress((void**)&vth, g_vt_hi); cudaGetSymbolAddress((void**)&vtl, g_vt_lo);
    cudaGetSymbolAddress((void**)&ch,  g_c_hi);  cudaGetSymbolAddress((void**)&cl,  g_c_lo);
    cudaGetSymbolAddress((void**)&x1h, g_x1_hi); cudaGetSymbolAddress((void**)&x1l, g_x1_lo);
    cudaGetSymbolAddress((void**)&hh,  g_h_hi);  cudaGetSymbolAddress((void**)&hl,  g_h_lo);
    cudaGetSymbolAddress((void**)&wth, g_wT_hi); cudaGetSymbolAddress((void**)&wtl, g_wT_lo);

    // dynamic smem: 2 stages * (2*A + 2*B) halves, BKP=40, bf16
    constexpr int SM128 = 2 * (2*(128*40) + 2*(128*40)) * 2;   // 81920 B
    constexpr int SM64  = 2 * (2*(128*40) + 2*(64*40))  * 2;   // 61440 B
    cudaFuncSetAttribute(bgemm<128,0>, cudaFuncAttributeMaxDynamicSharedMemorySize, SM128);
    cudaFuncSetAttribute(bgemm<128,1>, cudaFuncAttributeMaxDynamicSharedMemorySize, SM128);
    cudaFuncSetAttribute(bgemm<128,2>, cudaFuncAttributeMaxDynamicSharedMemorySize, SM128);
    cudaFuncSetAttribute(bgemm<64,1>,  cudaFuncAttributeMaxDynamicSharedMemorySize, SM64);

    const long long SS = (long long)SEQ*SEQ;
    const long long SE = (long long)SEQ*EMBED;

    // prep: split x; transpose+split all weights to [out][in]
    split_fp32<<<NTOK*EMBED/4/256, 256>>>(x, xh, xl, NTOK*EMBED/4);
    transpose_split<<<dim3(32,32,1),  256>>>(Wq, 0,0,1, EMBED, wth+OFF_WQ, wtl+OFF_WQ, 0, EMBED);
    transpose_split<<<dim3(32,32,1),  256>>>(Wk, 0,0,1, EMBED, wth+OFF_WK, wtl+OFF_WK, 0, EMBED);
    transpose_split<<<dim3(32,32,1),  256>>>(Wv, 0,0,1, EMBED, wth+OFF_WV, wtl+OFF_WV, 0, EMBED);
    transpose_split<<<dim3(32,32,1),  256>>>(Wo, 0,0,1, EMBED, wth+OFF_WO, wtl+OFF_WO, 0, EMBED);
    transpose_split<<<dim3(128,32,1), 256>>>(W1, 0,0,1, HIDDEN, wth+OFF_W1, wtl+OFF_W1, 0, EMBED);
    transpose_split<<<dim3(32,128,1), 256>>>(W2, 0,0,1, EMBED,  wth+OFF_W2, wtl+OFF_W2, 0, HIDDEN);

    // Q,K: split bf16 out; V: fp32 out (transposed next)
    dim3 gP(8, 32, 1);
    bgemm<128,1><<<gP, 256, SM128>>>(xh, xl, EMBED, 0,0, wth+OFF_WQ, wtl+OFF_WQ, EMBED, 0,0,
                                     nullptr, qh, ql, EMBED, 0,0, bq, 1.f, EMBED, 1);
    bgemm<128,1><<<gP, 256, SM128>>>(xh, xl, EMBED, 0,0, wth+OFF_WK, wtl+OFF_WK, EMBED, 0,0,
                                     nullptr, kh, kl, EMBED, 0,0, bk, 1.f, EMBED, 1);
    bgemm<128,0><<<gP, 256, SM128>>>(xh, xl, EMBED, 0,0, wth+OFF_WV, wtl+OFF_WV, EMBED, 0,0,
                                     v, nullptr, nullptr, EMBED, 0,0, bv, 1.f, EMBED, 1);

    // scores = QK^T/8 : fp32
    dim3 gS(16, 16, NBH);
    bgemm<128,0><<<gS, 256, SM128>>>(qh, ql, EMBED, SE, HDIM, kh, kl, EMBED, SE, HDIM,
                                     scores, nullptr, nullptr, SEQ, (long long)HEADS*SS, SS,
                                     nullptr, 0.125f, HDIM, HEADS);

    softmax_split<<<NBH*SEQ, 256>>>(scores, ph, pl);

    // V^T per head: [64][2048] split bf16
    transpose_split<<<dim3(2,64,NBH), 256>>>(v, SE, HDIM, HEADS, EMBED,
                                             vth, vtl, (long long)HDIM*SEQ, SEQ);

    // ctx = P @ V : N=64 per head, split bf16 out
    dim3 gC(1, 16, NBH);
    bgemm<64,1><<<gC, 256, SM64>>>(ph, pl, SEQ, (long long)HEADS*SS, SS,
                                   vth, vtl, SEQ, (long long)HEADS*HDIM*SEQ, (long long)HDIM*SEQ,
                                   nullptr, ch, cl, EMBED, SE, HDIM,
                                   nullptr, 1.f, SEQ, HEADS);

    // attn_out = ctx @ Wo + bo (fp32)
    bgemm<128,0><<<gP, 256, SM128>>>(ch, cl, EMBED, 0,0, wth+OFF_WO, wtl+OFF_WO, EMBED, 0,0,
                                     tmp, nullptr, nullptr, EMBED, 0,0, bo, 1.f, EMBED, 1);

    add_ln<true><<<NTOK, 256>>>(x, tmp, g1, be1, x1, x1h, x1l);

    // h = relu(x1 @ W1 + b1): split bf16
    dim3 gF(32, 32, 1);
    bgemm<128,2><<<gF, 256, SM128>>>(x1h, x1l, EMBED, 0,0, wth+OFF_W1, wtl+OFF_W1, EMBED, 0,0,
                                     nullptr, hh, hl, HIDDEN, 0,0, b1, 1.f, EMBED, 1);

    // f2 = h @ W2 + b2 (fp32)
    bgemm<128,0><<<gP, 256, SM128>>>(hh, hl, HIDDEN, 0,0, wth+OFF_W2, wtl+OFF_W2, HIDDEN, 0,0,
                                     tmp, nullptr, nullptr, EMBED, 0,0, b2, 1.f, HIDDEN, 1);

    add_ln<false><<<NTOK, 256>>>(x1, tmp, g2, be2, out, nullptr, nullptr);
}

// round 5
// speedup vs baseline: 3.0172x; 1.1486x over previous
#include <cuda_runtime.h>
#include <cuda_bf16.h>
#include <cstdint>

#define EMBED  1024
#define HEADS  16
#define HDIM   64
#define HIDDEN 4096
#define SEQ    2048
#define BATCH  2
#define NTOK   (BATCH*SEQ)
#define NBH    (BATCH*HEADS)

typedef __nv_bfloat16 bf16;

// ---------------- static scratch --------------------------------------------
__device__ bf16  g_x_hi[NTOK*EMBED],  g_x_lo[NTOK*EMBED];
__device__ bf16  g_q_hi[NTOK*EMBED],  g_q_lo[NTOK*EMBED];
__device__ bf16  g_k_hi[NTOK*EMBED],  g_k_lo[NTOK*EMBED];
__device__ float g_v[NTOK*EMBED];
__device__ bf16  g_vt_hi[NTOK*EMBED], g_vt_lo[NTOK*EMBED];   // [b,h][64][2048]
__device__ bf16  g_c_hi[NTOK*EMBED],  g_c_lo[NTOK*EMBED];
__device__ float g_tmp[NTOK*EMBED];
__device__ float g_x1[NTOK*EMBED];
__device__ bf16  g_x1_hi[NTOK*EMBED], g_x1_lo[NTOK*EMBED];
__device__ bf16  g_h_hi[(size_t)NTOK*HIDDEN], g_h_lo[(size_t)NTOK*HIDDEN];
__device__ bf16  g_wT_hi[12*1024*1024], g_wT_lo[12*1024*1024];
#define OFF_WQ 0
#define OFF_WK (1*1024*1024)
#define OFF_WV (2*1024*1024)
#define OFF_WO (3*1024*1024)
#define OFF_W1 (4*1024*1024)
#define OFF_W2 (8*1024*1024)

// ---------------- helpers ----------------------------------------------------
__device__ __forceinline__ uint32_t smem_u32(const void* p) {
    uint32_t a;
    asm("{ .reg .u64 t; cvta.to.shared.u64 t, %1; cvt.u32.u64 %0, t; }" : "=r"(a) : "l"(p));
    return a;
}
__device__ __forceinline__ void cp16(const void* smem_dst, const void* gsrc) {
    uint32_t d = smem_u32(smem_dst);
    asm volatile("cp.async.cg.shared.global [%0], [%1], 16;" :: "r"(d), "l"(gsrc) : "memory");
}
#define CP_COMMIT() asm volatile("cp.async.commit_group;" ::: "memory")
#define CP_WAIT(n)  asm volatile("cp.async.wait_group %0;" :: "n"(n) : "memory")

__device__ __forceinline__ void mma16816(float* c, const uint32_t* a, const uint32_t* b) {
    asm volatile("mma.sync.aligned.m16n8k16.row.col.f32.bf16.bf16.f32 "
        "{%0,%1,%2,%3}, {%4,%5,%6,%7}, {%8,%9}, {%0,%1,%2,%3};"
        : "+f"(c[0]), "+f"(c[1]), "+f"(c[2]), "+f"(c[3])
        : "r"(a[0]), "r"(a[1]), "r"(a[2]), "r"(a[3]), "r"(b[0]), "r"(b[1]));
}
__device__ __forceinline__ void fsplit(float v, bf16& h, bf16& l) {
    h = __float2bfloat16_rn(v);
    l = __float2bfloat16_rn(v - __bfloat162float(h));
}
__device__ __forceinline__ uint32_t pack2(bf16 a, bf16 b) {
    __nv_bfloat162 t; t.x = a; t.y = b; return *(uint32_t*)&t;
}

// ---------------- bf16x3 HMMA GEMM (unchanged from R4, proven) ---------------
template<int BN, int EPI>
__global__ void __launch_bounds__(256)
bgemm(const bf16* __restrict__ Ah, const bf16* __restrict__ Al, int lda,
      long long aOut, long long aIn,
      const bf16* __restrict__ Bh, const bf16* __restrict__ Bl, int ldb,
      long long bOut, long long bIn,
      float* Cf, bf16* Ch, bf16* Cl, int ldc, long long cOut, long long cIn,
      const float* __restrict__ bias, float alpha, int K, int inner)
{
    constexpr int BM = 128, BK = 32, BKP = 40;
    constexpr int WM = (BN == 128) ? 2 : 4, WN = 8 / WM;
    constexpr int WTM = BM / WM, WTN = BN / WN;
    constexpr int MI = WTM / 16, NI = WTN / 8;
    constexpr int ASZ = BM * BKP;
    constexpr int BSZ = BN * BKP;
    constexpr int SST = 2*ASZ + 2*BSZ;
    constexpr int CHA = BM * 4 * 2;
    constexpr int CHB = BN * 4 * 2;
    constexpr int ITER = (CHA + CHB) / 256;

    extern __shared__ bf16 sm[];

    const int tid = threadIdx.x;
    const int warp = tid >> 5, lane = tid & 31;
    const int g = lane >> 2, t4 = lane & 3;
    const int wm = (warp % WM) * WTM;
    const int wn = (warp / WM) * WTN;

    const int z = blockIdx.z, ob = z / inner, oi = z - ob*inner;
    Ah += (long long)ob*aOut + (long long)oi*aIn;
    Al += (long long)ob*aOut + (long long)oi*aIn;
    Bh += (long long)ob*bOut + (long long)oi*bIn;
    Bl += (long long)ob*bOut + (long long)oi*bIn;
    const long long coff = (long long)ob*cOut + (long long)oi*cIn;
    if (EPI == 0) Cf += coff; else { Ch += coff; Cl += coff; }

    const int rowBase = blockIdx.y * BM;
    const int colBase = blockIdx.x * BN;

    float acc[MI][NI][4];
#pragma unroll
    for (int mi = 0; mi < MI; mi++)
#pragma unroll
        for (int ni = 0; ni < NI; ni++)
#pragma unroll
            for (int i = 0; i < 4; i++) acc[mi][ni][i] = 0.f;

    auto load_stage = [&](int s, int k0) {
        bf16* st = sm + s * SST;
#pragma unroll
        for (int i = 0; i < ITER; i++) {
            int idx = i * 256 + tid;
            if (idx < CHA) {
                int half = idx >> 9;
                int r    = (idx >> 2) & (BM - 1);
                int c    = idx & 3;
                const bf16* src = (half ? Al : Ah) + (size_t)(rowBase + r)*lda + k0 + c*8;
                cp16(st + half*ASZ + r*BKP + c*8, src);
            } else {
                int j = idx - CHA;
                int half = j / (BN * 4);
                int r    = (j >> 2) % BN;
                int c    = j & 3;
                const bf16* src = (half ? Bl : Bh) + (size_t)(colBase + r)*ldb + k0 + c*8;
                cp16(st + 2*ASZ + half*BSZ + r*BKP + c*8, src);
            }
        }
    };

    const int T = K / BK;
    load_stage(0, 0);
    CP_COMMIT();

    for (int t = 0; t < T; t++) {
        if (t + 1 < T) {
            load_stage((t + 1) & 1, (t + 1) * BK);
            CP_COMMIT();
            CP_WAIT(1);
        } else {
            CP_WAIT(0);
        }
        __syncthreads();

        const bf16* sAh = sm + (t & 1) * SST;
        const bf16* sAl = sAh + ASZ;
        const bf16* sBh = sAl + ASZ;
        const bf16* sBl = sBh + BSZ;

#pragma unroll
        for (int kk = 0; kk < BK; kk += 16) {
            uint32_t ah[MI][4], al[MI][4];
#pragma unroll
            for (int mi = 0; mi < MI; mi++) {
                int r0 = wm + mi*16 + g;
                int c0 = kk + t4*2;
                ah[mi][0] = *(const uint32_t*)&sAh[(r0  )*BKP + c0    ];
                ah[mi][1] = *(const uint32_t*)&sAh[(r0+8)*BKP + c0    ];
                ah[mi][2] = *(const uint32_t*)&sAh[(r0  )*BKP + c0 + 8];
                ah[mi][3] = *(const uint32_t*)&sAh[(r0+8)*BKP + c0 + 8];
                al[mi][0] = *(const uint32_t*)&sAl[(r0  )*BKP + c0    ];
                al[mi][1] = *(const uint32_t*)&sAl[(r0+8)*BKP + c0    ];
                al[mi][2] = *(const uint32_t*)&sAl[(r0  )*BKP + c0 + 8];
                al[mi][3] = *(const uint32_t*)&sAl[(r0+8)*BKP + c0 + 8];
            }
            uint32_t bh[NI][2], bl[NI][2];
#pragma unroll
            for (int ni = 0; ni < NI; ni++) {
                int rn = wn + ni*8 + g;
                int ck = kk + t4*2;
                bh[ni][0] = *(const uint32_t*)&sBh[rn*BKP + ck    ];
                bh[ni][1] = *(const uint32_t*)&sBh[rn*BKP + ck + 8];
                bl[ni][0] = *(const uint32_t*)&sBl[rn*BKP + ck    ];
                bl[ni][1] = *(const uint32_t*)&sBl[rn*BKP + ck + 8];
            }
#pragma unroll
            for (int mi = 0; mi < MI; mi++)
#pragma unroll
                for (int ni = 0; ni < NI; ni++) {
                    mma16816(acc[mi][ni], ah[mi], bh[ni]);
                    mma16816(acc[mi][ni], ah[mi], bl[ni]);
                    mma16816(acc[mi][ni], al[mi], bh[ni]);
                }
        }
        __syncthreads();
    }

#pragma unroll
    for (int ni = 0; ni < NI; ni++) {
        int col = colBase + wn + ni*8 + t4*2;
        float b0 = 0.f, b1 = 0.f;
        if (bias) { b0 = __ldg(bias + col); b1 = __ldg(bias + col + 1); }
#pragma unroll
        for (int mi = 0; mi < MI; mi++) {
            int row0 = rowBase + wm + mi*16 + g;
            float v0 = acc[mi][ni][0] * alpha + b0;
            float v1 = acc[mi][ni][1] * alpha + b1;
            float v2 = acc[mi][ni][2] * alpha + b0;
            float v3 = acc[mi][ni][3] * alpha + b1;
            if (EPI == 2) {
                v0 = fmaxf(v0, 0.f); v1 = fmaxf(v1, 0.f);
                v2 = fmaxf(v2, 0.f); v3 = fmaxf(v3, 0.f);
            }
            if (EPI == 0) {
                float2 r01; r01.x = v0; r01.y = v1;
                float2 r23; r23.x = v2; r23.y = v3;
                *(float2*)(Cf + (size_t)row0     * ldc + col) = r01;
                *(float2*)(Cf + (size_t)(row0+8) * ldc + col) = r23;
            } else {
                bf16 h0,l0,h1,l1,h2,l2,h3,l3;
                fsplit(v0,h0,l0); fsplit(v1,h1,l1);
                fsplit(v2,h2,l2); fsplit(v3,h3,l3);
                *(uint32_t*)(Ch + (size_t)row0     * ldc + col) = pack2(h0,h1);
                *(uint32_t*)(Cl + (size_t)row0     * ldc + col) = pack2(l0,l1);
                *(uint32_t*)(Ch + (size_t)(row0+8) * ldc + col) = pack2(h2,h3);
                *(uint32_t*)(Cl + (size_t)(row0+8) * ldc + col) = pack2(l2,l3);
            }
        }
    }
}

// ---------------- fused flash attention (bf16x3) ------------------------------
// One block = one (b,h) x 128 q-rows. Q frags in registers; K/V^T double-buffered.
// S acc -> in-register softmax (running max/sum) -> P hi/lo frags -> O += P*V.
__global__ void __launch_bounds__(256)
flash_attn(const bf16* __restrict__ qh, const bf16* __restrict__ ql,
           const bf16* __restrict__ kh, const bf16* __restrict__ kl,
           const bf16* __restrict__ vth, const bf16* __restrict__ vtl,
           bf16* __restrict__ ch, bf16* __restrict__ cl)
{
    constexpr int KP = 72, VP = 136;
    constexpr int SKH = 128*KP;          // elems per K half
    constexpr int SVH = 64*VP;           // elems per V^T half
    constexpr int STG = 2*SKH + 2*SVH;   // elems per stage

    extern __shared__ bf16 sm[];

    const int tid = threadIdx.x, warp = tid >> 5, lane = tid & 31;
    const int g = lane >> 2, t4 = lane & 3;
    const int wm = warp * 16;

    const int z = blockIdx.y;                 // b*HEADS + h
    const int b = z / HEADS, h = z - b*HEADS;
    const int hc = h * HDIM;
    const int qRow = b*SEQ + blockIdx.x*128;
    const int kvTok0 = b*SEQ;
    const size_t vbase = (size_t)z * HDIM * SEQ;

    // Q fragments: a-order {(g,k0),(g+8,k0),(g,k0+8),(g+8,k0+8)} packed bf16x2
    uint32_t qfh[4][4], qfl[4][4];
#pragma unroll
    for (int ks = 0; ks < 4; ks++) {
        size_t a0 = (size_t)(qRow + wm + g)*EMBED + hc + ks*16 + t4*2;
        qfh[ks][0] = *(const uint32_t*)(qh + a0);
        qfh[ks][1] = *(const uint32_t*)(qh + a0 + 8*EMBED);
        qfh[ks][2] = *(const uint32_t*)(qh + a0 + 8);
        qfh[ks][3] = *(const uint32_t*)(qh + a0 + 8*EMBED + 8);
        qfl[ks][0] = *(const uint32_t*)(ql + a0);
        qfl[ks][1] = *(const uint32_t*)(ql + a0 + 8*EMBED);
        qfl[ks][2] = *(const uint32_t*)(ql + a0 + 8);
        qfl[ks][3] = *(const uint32_t*)(ql + a0 + 8*EMBED + 8);
    }

    float oacc[8][4];
#pragma unroll
    for (int ni = 0; ni < 8; ni++)
#pragma unroll
        for (int j = 0; j < 4; j++) oacc[ni][j] = 0.f;
    float m0 = -1e30f, m1 = -1e30f, l0 = 0.f, l1 = 0.f;

    auto load_stage = [&](int s, int kt) {
        bf16* st = sm + s * STG;
        const int kvB = kvTok0 + kt*128;
#pragma unroll
        for (int i = 0; i < 16; i++) {
            int idx = i*256 + tid;
            if (idx < 2048) {                                  // K tile
                int half = idx >> 10, r = (idx >> 3) & 127, c = idx & 7;
                const bf16* src = (half ? kl : kh) + (size_t)(kvB + r)*EMBED + hc + c*8;
                cp16(st + half*SKH + r*KP + c*8, src);
            } else {                                           // V^T tile
                int j = idx - 2048;
                int half = j >> 10, r = (j >> 4) & 63, c = j & 15;
                const bf16* src = (half ? vtl : vth) + vbase + (size_t)r*SEQ + kt*128 + c*8;
                cp16(st + 2*SKH + half*SVH + r*VP + c*8, src);
            }
        }
    };

    load_stage(0, 0);
    CP_COMMIT();

    for (int kt = 0; kt < SEQ/128; kt++) {
        if (kt + 1 < SEQ/128) { load_stage((kt+1)&1, kt+1); CP_COMMIT(); CP_WAIT(1); }
        else CP_WAIT(0);
        __syncthreads();

        const bf16* sKh = sm + (kt & 1) * STG;
        const bf16* sKl = sKh + SKH;
        const bf16* sVh = sKl + SKH;
        const bf16* sVl = sVh + SVH;

        // ---- S = Q K^T (128x128), bf16x3 -----------------------------------
        float sacc[16][4];
#pragma unroll
        for (int ni = 0; ni < 16; ni++)
#pragma unroll
            for (int j = 0; j < 4; j++) sacc[ni][j] = 0.f;

#pragma unroll
        for (int ks = 0; ks < 4; ks++) {
            const int ck = ks*16 + t4*2;
#pragma unroll
            for (int ni = 0; ni < 16; ni++) {
                const int rn = ni*8 + g;
                uint32_t bh[2], bl[2];
                bh[0] = *(const uint32_t*)&sKh[rn*KP + ck];
                bh[1] = *(const uint32_t*)&sKh[rn*KP + ck + 8];
                bl[0] = *(const uint32_t*)&sKl[rn*KP + ck];
                bl[1] = *(const uint32_t*)&sKl[rn*KP + ck + 8];
                mma16816(sacc[ni], qfh[ks], bh);
                mma16816(sacc[ni], qfh[ks], bl);
                mma16816(sacc[ni], qfl[ks], bh);
            }
        }

        // ---- running softmax over the 128 new cols --------------------------
        float mt0 = -1e30f, mt1 = -1e30f;
#pragma unroll
        for (int ni = 0; ni < 16; ni++) {
#pragma unroll
            for (int j = 0; j < 4; j++) sacc[ni][j] *= 0.125f;
            mt0 = fmaxf(mt0, fmaxf(sacc[ni][0], sacc[ni][1]));
            mt1 = fmaxf(mt1, fmaxf(sacc[ni][2], sacc[ni][3]));
        }
        mt0 = fmaxf(mt0, __shfl_xor_sync(~0u, mt0, 1));
        mt0 = fmaxf(mt0, __shfl_xor_sync(~0u, mt0, 2));
        mt1 = fmaxf(mt1, __shfl_xor_sync(~0u, mt1, 1));
        mt1 = fmaxf(mt1, __shfl_xor_sync(~0u, mt1, 2));

        const float mn0 = fmaxf(m0, mt0), mn1 = fmaxf(m1, mt1);
        const float sc0 = __expf(m0 - mn0), sc1 = __expf(m1 - mn1);

        float ls0 = 0.f, ls1 = 0.f;
#pragma unroll
        for (int ni = 0; ni < 16; ni++) {
            sacc[ni][0] = __expf(sacc[ni][0] - mn0);
            sacc[ni][1] = __expf(sacc[ni][1] - mn0);
            sacc[ni][2] = __expf(sacc[ni][2] - mn1);
            sacc[ni][3] = __expf(sacc[ni][3] - mn1);
            ls0 += sacc[ni][0] + sacc[ni][1];
            ls1 += sacc[ni][2] + sacc[ni][3];
        }
        ls0 += __shfl_xor_sync(~0u, ls0, 1); ls0 += __shfl_xor_sync(~0u, ls0, 2);
        ls1 += __shfl_xor_sync(~0u, ls1, 1); ls1 += __shfl_xor_sync(~0u, ls1, 2);

        l0 = l0*sc0 + ls0; l1 = l1*sc1 + ls1;
        m0 = mn0; m1 = mn1;
#pragma unroll
        for (int ni = 0; ni < 8; ni++) {
            oacc[ni][0] *= sc0; oacc[ni][1] *= sc0;
            oacc[ni][2] *= sc1; oacc[ni][3] *= sc1;
        }

        // ---- pack P into A-fragments (hi/lo) --------------------------------
        uint32_t pfh[8][4], pfl[8][4];
#pragma unroll
        for (int k2 = 0; k2 < 8; k2++) {
            const float* cA = sacc[2*k2];
            const float* cB = sacc[2*k2 + 1];
            bf16 ha, la, hb, lb;
            fsplit(cA[0], ha, la); fsplit(cA[1], hb, lb);
            pfh[k2][0] = pack2(ha, hb); pfl[k2][0] = pack2(la, lb);
            fsplit(cA[2], ha, la); fsplit(cA[3], hb, lb);
            pfh[k2][1] = pack2(ha, hb); pfl[k2][1] = pack2(la, lb);
            fsplit(cB[0], ha, la); fsplit(cB[1], hb, lb);
            pfh[k2][2] = pack2(ha, hb); pfl[k2][2] = pack2(la, lb);
            fsplit(cB[2], ha, la); fsplit(cB[3], hb, lb);
            pfh[k2][3] = pack2(ha, hb); pfl[k2][3] = pack2(la, lb);
        }

        // ---- O += P V (128x128 @ 128x64), bf16x3 ----------------------------
#pragma unroll
        for (int ni = 0; ni < 8; ni++) {
            const int vn = ni*8 + g;
#pragma unroll
            for (int k2 = 0; k2 < 8; k2++) {
                const int ck2 = k2*16 + t4*2;
                uint32_t vbh[2], vbl[2];
                vbh[0] = *(const uint32_t*)&sVh[vn*VP + ck2];
                vbh[1] = *(const uint32_t*)&sVh[vn*VP + ck2 + 8];
                vbl[0] = *(const uint32_t*)&sVl[vn*VP + ck2];
                vbl[1] = *(const uint32_t*)&sVl[vn*VP + ck2 + 8];
                mma16816(oacc[ni], pfh[k2], vbh);
                mma16816(oacc[ni], pfh[k2], vbl);
                mma16816(oacc[ni], pfl[k2], vbh);
            }
        }
        __syncthreads();
    }

    // ---- epilogue: ctx = O / l, split hi/lo ---------------------------------
    const float i0 = 1.f / l0, i1 = 1.f / l1;
#pragma unroll
    for (int ni = 0; ni < 8; ni++) {
        const int col = hc + ni*8 + t4*2;
        const size_t r0 = (size_t)(qRow + wm + g)*EMBED + col;
        const size_t r1 = r0 + 8*EMBED;
        float v0 = oacc[ni][0]*i0, v1 = oacc[ni][1]*i0;
        float v2 = oacc[ni][2]*i1, v3 = oacc[ni][3]*i1;
        bf16 ha, la, hb, lb;
        fsplit(v0, ha, la); fsplit(v1, hb, lb);
        *(uint32_t*)(ch + r0) = pack2(ha, hb);
        *(uint32_t*)(cl + r0) = pack2(la, lb);
        fsplit(v2, ha, la); fsplit(v3, hb, lb);
        *(uint32_t*)(ch + r1) = pack2(ha, hb);
        *(uint32_t*)(cl + r1) = pack2(la, lb);
    }
}

// ---------------- split fp32 -> hi/lo bf16 -----------------------------------
__global__ void __launch_bounds__(256) split_fp32(const float* __restrict__ in,
                                                  bf16* __restrict__ oh,
                                                  bf16* __restrict__ ol, int n4)
{
    int i = blockIdx.x*256 + threadIdx.x;
    if (i >= n4) return;
    float4 v = ((const float4*)in)[i];
    bf16 h[4], l[4];
    fsplit(v.x,h[0],l[0]); fsplit(v.y,h[1],l[1]);
    fsplit(v.z,h[2],l[2]); fsplit(v.w,h[3],l[3]);
    uint2 uh; uh.x = pack2(h[0],h[1]); uh.y = pack2(h[2],h[3]);
    uint2 ul; ul.x = pack2(l[0],l[1]); ul.y = pack2(l[2],l[3]);
    ((uint2*)oh)[i] = uh;
    ((uint2*)ol)[i] = ul;
}

// ---------------- batched transpose+split fp32[R,C] -> bf16 [C,R] ------------
__global__ void __launch_bounds__(256)
transpose_split(const float* __restrict__ in, long long inOuter, long long inInner,
                int innerB, int ldi,
                bf16* __restrict__ oh, bf16* __restrict__ ol,
                long long outStride, int ldo)
{
    __shared__ float tile[32][33];
    const int z = blockIdx.z;
    const float* src = in + (long long)(z/innerB)*inOuter + (long long)(z%innerB)*inInner;
    bf16* dh = oh + (long long)z*outStride;
    bf16* dl = ol + (long long)z*outStride;
    const int c0 = blockIdx.x*32, r0 = blockIdx.y*32;
    const int tx = threadIdx.x & 31, ty = threadIdx.x >> 5;
#pragma unroll
    for (int i = 0; i < 4; i++)
        tile[ty + i*8][tx] = src[(long long)(r0 + ty + i*8)*ldi + c0 + tx];
    __syncthreads();
#pragma unroll
    for (int i = 0; i < 4; i++) {
        bf16 h, l; fsplit(tile[tx][ty + i*8], h, l);
        long long o = (long long)(c0 + ty + i*8)*ldo + r0 + tx;
        dh[o] = h; dl[o] = l;
    }
}

// ---------------- residual + LayerNorm (optional split out) -------------------
template<bool SPLIT>
__global__ void __launch_bounds__(256)
add_ln(const float* __restrict__ X, const float* __restrict__ Y,
       const float* __restrict__ gamma, const float* __restrict__ beta,
       float* __restrict__ O, bf16* __restrict__ Oh, bf16* __restrict__ Ol)
{
    const size_t base = (size_t)blockIdx.x * EMBED;
    const int tid = threadIdx.x;
    float4 xv = ((const float4*)(X + base))[tid];
    float4 yv = ((const float4*)(Y + base))[tid];
    float4 r; r.x=xv.x+yv.x; r.y=xv.y+yv.y; r.z=xv.z+yv.z; r.w=xv.w+yv.w;

    float s = r.x+r.y+r.z+r.w;
    float sq = r.x*r.x+r.y*r.y+r.z*r.z+r.w*r.w;
    __shared__ float rs[8], rq[8];
#pragma unroll
    for (int o = 16; o > 0; o >>= 1) {
        s += __shfl_xor_sync(~0u, s, o);
        sq += __shfl_xor_sync(~0u, sq, o);
    }
    const int wid = tid>>5, lane = tid&31;
    if (lane == 0) { rs[wid]=s; rq[wid]=sq; }
    __syncthreads();
    s = rs[0]; sq = rq[0];
#pragma unroll
    for (int w = 1; w < 8; w++) { s += rs[w]; sq += rq[w]; }

    const float mu = s * (1.f/EMBED);
    const float var = sq * (1.f/EMBED) - mu*mu;
    const float rstd = rsqrtf(var + 1e-6f);
    float4 g = ((const float4*)gamma)[tid];
    float4 bb = ((const float4*)beta)[tid];
    float4 o;
    o.x=(r.x-mu)*rstd*g.x+bb.x; o.y=(r.y-mu)*rstd*g.y+bb.y;
    o.z=(r.z-mu)*rstd*g.z+bb.z; o.w=(r.w-mu)*rstd*g.w+bb.w;
    ((float4*)(O + base))[tid] = o;
    if (SPLIT) {
        bf16 h[4], l[4];
        fsplit(o.x,h[0],l[0]); fsplit(o.y,h[1],l[1]);
        fsplit(o.z,h[2],l[2]); fsplit(o.w,h[3],l[3]);
        uint2 uh; uh.x=pack2(h[0],h[1]); uh.y=pack2(h[2],h[3]);
        uint2 ul; ul.x=pack2(l[0],l[1]); ul.y=pack2(l[2],l[3]);
        ((uint2*)(Oh + base))[tid] = uh;
        ((uint2*)(Ol + base))[tid] = ul;
    }
}

// ---------------- host --------------------------------------------------------
extern "C" void kernel_launch(void* const* d_in, const int* in_sizes, int n_in,
                              void* d_out, int out_size)
{
    const float* x  = (const float*)d_in[0];
    const float* Wq = (const float*)d_in[1];  const float* bq = (const float*)d_in[2];
    const float* Wk = (const float*)d_in[3];  const float* bk = (const float*)d_in[4];
    const float* Wv = (const float*)d_in[5];  const float* bv = (const float*)d_in[6];
    const float* Wo = (const float*)d_in[7];  const float* bo = (const float*)d_in[8];
    const float* g1 = (const float*)d_in[9];  const float* be1 = (const float*)d_in[10];
    const float* W1 = (const float*)d_in[11]; const float* b1 = (const float*)d_in[12];
    const float* W2 = (const float*)d_in[13]; const float* b2 = (const float*)d_in[14];
    const float* g2 = (const float*)d_in[15]; const float* be2 = (const float*)d_in[16];
    float* out = (float*)d_out;

    float *v, *tmp, *x1;
    bf16 *xh,*xl,*qh,*ql,*kh,*kl,*vth,*vtl,*ch,*cl,*x1h,*x1l,*hh,*hl,*wth,*wtl;
    cudaGetSymbolAddress((void**)&v,   g_v);
    cudaGetSymbolAddress((void**)&tmp, g_tmp);
    cudaGetSymbolAddress((void**)&x1,  g_x1);
    cudaGetSymbolAddress((void**)&xh,  g_x_hi);  cudaGetSymbolAddress((void**)&xl,  g_x_lo);
    cudaGetSymbolAddress((void**)&qh,  g_q_hi);  cudaGetSymbolAddress((void**)&ql,  g_q_lo);
    cudaGetSymbolAddress((void**)&kh,  g_k_hi);  cudaGetSymbolAddress((void**)&kl,  g_k_lo);
    cudaGetSymbolAddress((void**)&vth, g_vt_hi); cudaGetSymbolAddress((void**)&vtl, g_vt_lo);
    cudaGetSymbolAddress((void**)&ch,  g_c_hi);  cudaGetSymbolAddress((void**)&cl,  g_c_lo);
    cudaGetSymbolAddress((void**)&x1h, g_x1_hi); cudaGetSymbolAddress((void**)&x1l, g_x1_lo);
    cudaGetSymbolAddress((void**)&hh,  g_h_hi);  cudaGetSymbolAddress((void**)&hl,  g_h_lo);
    cudaGetSymbolAddress((void**)&wth, g_wT_hi); cudaGetSymbolAddress((void**)&wtl, g_wT_lo);

    constexpr int SM128 = 2 * (2*(128*40) + 2*(128*40)) * 2;   // 81920 B
    constexpr int FASM  = (2*(128*72) + 2*(64*136)) * 2 * 2;   // 143360 B
    cudaFuncSetAttribute(bgemm<128,0>, cudaFuncAttributeMaxDynamicSharedMemorySize, SM128);
    cudaFuncSetAttribute(bgemm<128,1>, cudaFuncAttributeMaxDynamicSharedMemorySize, SM128);
    cudaFuncSetAttribute(bgemm<128,2>, cudaFuncAttributeMaxDynamicSharedMemorySize, SM128);
    cudaFuncSetAttribute(flash_attn,   cudaFuncAttributeMaxDynamicSharedMemorySize, FASM);

    const long long SE = (long long)SEQ*EMBED;

    // prep: split x; transpose+split all weights to [out][in]
    split_fp32<<<NTOK*EMBED/4/256, 256>>>(x, xh, xl, NTOK*EMBED/4);
    transpose_split<<<dim3(32,32,1),  256>>>(Wq, 0,0,1, EMBED, wth+OFF_WQ, wtl+OFF_WQ, 0, EMBED);
    transpose_split<<<dim3(32,32,1),  256>>>(Wk, 0,0,1, EMBED, wth+OFF_WK, wtl+OFF_WK, 0, EMBED);
    transpose_split<<<dim3(32,32,1),  256>>>(Wv, 0,0,1, EMBED, wth+OFF_WV, wtl+OFF_WV, 0, EMBED);
    transpose_split<<<dim3(32,32,1),  256>>>(Wo, 0,0,1, EMBED, wth+OFF_WO, wtl+OFF_WO, 0, EMBED);
    transpose_split<<<dim3(128,32,1), 256>>>(W1, 0,0,1, HIDDEN, wth+OFF_W1, wtl+OFF_W1, 0, EMBED);
    transpose_split<<<dim3(32,128,1), 256>>>(W2, 0,0,1, EMBED,  wth+OFF_W2, wtl+OFF_W2, 0, HIDDEN);

    // Q,K: split bf16; V: fp32 (transposed next)
    dim3 gP(8, 32, 1);
    bgemm<128,1><<<gP, 256, SM128>>>(xh, xl, EMBED, 0,0, wth+OFF_WQ, wtl+OFF_WQ, EMBED, 0,0,
                                     nullptr, qh, ql, EMBED, 0,0, bq, 1.f, EMBED, 1);
    bgemm<128,1><<<gP, 256, SM128>>>(xh, xl, EMBED, 0,0, wth+OFF_WK, wtl+OFF_WK, EMBED, 0,0,
                                     nullptr, kh, kl, EMBED, 0,0, bk, 1.f, EMBED, 1);
    bgemm<128,0><<<gP, 256, SM128>>>(xh, xl, EMBED, 0,0, wth+OFF_WV, wtl+OFF_WV, EMBED, 0,0,
                                     v, nullptr, nullptr, EMBED, 0,0, bv, 1.f, EMBED, 1);

    // V^T per head: [64][2048] split bf16
    transpose_split<<<dim3(2,64,NBH), 256>>>(v, SE, HDIM, HEADS, EMBED,
                                             vth, vtl, (long long)HDIM*SEQ, SEQ);

    // fused attention: scores + softmax + P@V -> ctx (split bf16)
    flash_attn<<<dim3(SEQ/128, NBH), 256, FASM>>>(qh, ql, kh, kl, vth, vtl, ch, cl);

    // attn_out = ctx @ Wo + bo (fp32)
    bgemm<128,0><<<gP, 256, SM128>>>(ch, cl, EMBED, 0,0, wth+OFF_WO, wtl+OFF_WO, EMBED, 0,0,
                                     tmp, nullptr, nullptr, EMBED, 0,0, bo, 1.f, EMBED, 1);

    add_ln<true><<<NTOK, 256>>>(x, tmp, g1, be1, x1, x1h, x1l);

    // h = relu(x1 @ W1 + b1): split bf16
    dim3 gF(32, 32, 1);
    bgemm<128,2><<<gF, 256, SM128>>>(x1h, x1l, EMBED, 0,0, wth+OFF_W1, wtl+OFF_W1, EMBED, 0,0,
                                     nullptr, hh, hl, HIDDEN, 0,0, b1, 1.f, EMBED, 1);

    // f2 = h @ W2 + b2 (fp32)
    bgemm<128,0><<<gP, 256, SM128>>>(hh, hl, HIDDEN, 0,0, wth+OFF_W2, wtl+OFF_W2, HIDDEN, 0,0,
                                     tmp, nullptr, nullptr, EMBED, 0,0, b2, 1.f, HIDDEN, 1);

    add_ln<false><<<NTOK, 256>>>(x1, tmp, g2, be2, out, nullptr, nullptr);
}

// round 6
// speedup vs baseline: 4.2792x; 1.4182x over previous
#include <cuda_runtime.h>
#include <cuda_fp16.h>
#include <cstdint>

#define EMBED  1024
#define HEADS  16
#define HDIM   64
#define HIDDEN 4096
#define SEQ    2048
#define BATCH  2
#define NTOK   (BATCH*SEQ)
#define NBH    (BATCH*HEADS)

typedef __half hf;

// ---------------- static scratch --------------------------------------------
__device__ hf    g_x_hi[NTOK*EMBED];
__device__ hf    g_q_hi[NTOK*EMBED];
__device__ hf    g_k_hi[NTOK*EMBED],  g_k_lo[NTOK*EMBED];
__device__ float g_v[NTOK*EMBED];
__device__ hf    g_vt_hi[NTOK*EMBED], g_vt_lo[NTOK*EMBED];   // [b,h][64][2048]
__device__ hf    g_c_hi[NTOK*EMBED];
__device__ float g_tmp[NTOK*EMBED];
__device__ float g_x1[NTOK*EMBED];
__device__ hf    g_x1_hi[NTOK*EMBED];
__device__ hf    g_h_hi[(size_t)NTOK*HIDDEN];
__device__ hf    g_wT_hi[12*1024*1024], g_wT_lo[12*1024*1024];
#define OFF_WQ 0
#define OFF_WK (1*1024*1024)
#define OFF_WV (2*1024*1024)
#define OFF_WO (3*1024*1024)
#define OFF_W1 (4*1024*1024)
#define OFF_W2 (8*1024*1024)

// ---------------- helpers ----------------------------------------------------
__device__ __forceinline__ uint32_t smem_u32(const void* p) {
    uint32_t a;
    asm("{ .reg .u64 t; cvta.to.shared.u64 t, %1; cvt.u32.u64 %0, t; }" : "=r"(a) : "l"(p));
    return a;
}
__device__ __forceinline__ void cp16(const void* smem_dst, const void* gsrc) {
    uint32_t d = smem_u32(smem_dst);
    asm volatile("cp.async.cg.shared.global [%0], [%1], 16;" :: "r"(d), "l"(gsrc) : "memory");
}
#define CP_COMMIT() asm volatile("cp.async.commit_group;" ::: "memory")
#define CP_WAIT(n)  asm volatile("cp.async.wait_group %0;" :: "n"(n) : "memory")

__device__ __forceinline__ void mma16816(float* c, const uint32_t* a, const uint32_t* b) {
    asm volatile("mma.sync.aligned.m16n8k16.row.col.f32.f16.f16.f32 "
        "{%0,%1,%2,%3}, {%4,%5,%6,%7}, {%8,%9}, {%0,%1,%2,%3};"
        : "+f"(c[0]), "+f"(c[1]), "+f"(c[2]), "+f"(c[3])
        : "r"(a[0]), "r"(a[1]), "r"(a[2]), "r"(a[3]), "r"(b[0]), "r"(b[1]));
}
__device__ __forceinline__ void fsplit(float v, hf& h, hf& l) {
    h = __float2half_rn(v);
    l = __float2half_rn(v - __half2float(h));
}
__device__ __forceinline__ uint32_t pack2(hf a, hf b) {
    __half2 t; t.x = a; t.y = b; return *(uint32_t*)&t;
}

// ---------------- fp16x2 HMMA GEMM --------------------------------------------
// D[M,N] = alpha*sum_k A[m,k]*B[n,k] (+bias)(+relu). A fp16, B hi/lo fp16 pair.
// BM=128, BK=32, double-buffered cp.async. 256 threads = 8 warps.
// EPI: 0 = fp32 out, 1 = fp16 hi(+optional lo) out, 2 = relu + fp16 out
template<int BN, int EPI>
__global__ void __launch_bounds__(256)
bgemm(const hf* __restrict__ Ah, int lda, long long aOut, long long aIn,
      const hf* __restrict__ Bh, const hf* __restrict__ Bl, int ldb,
      long long bOut, long long bIn,
      float* Cf, hf* Ch, hf* Cl, int ldc, long long cOut, long long cIn,
      const float* __restrict__ bias, float alpha, int K, int inner)
{
    constexpr int BM = 128, BK = 32, BKP = 40;
    constexpr int WM = 2, WN = 4;
    constexpr int WTM = BM / WM, WTN = BN / WN;
    constexpr int MI = WTM / 16, NI = WTN / 8;
    constexpr int ASZ = BM * BKP;
    constexpr int BSZ = BN * BKP;
    constexpr int SST = ASZ + 2*BSZ;
    constexpr int CHA = BM * 4;            // 16B chunks, A hi only
    constexpr int CHB = BN * 4 * 2;
    constexpr int ITER = (CHA + CHB) / 256;

    extern __shared__ hf sm[];

    const int tid = threadIdx.x;
    const int warp = tid >> 5, lane = tid & 31;
    const int g = lane >> 2, t4 = lane & 3;
    const int wm = (warp % WM) * WTM;
    const int wn = (warp / WM) * WTN;

    const int z = blockIdx.z, ob = z / inner, oi = z - ob*inner;
    Ah += (long long)ob*aOut + (long long)oi*aIn;
    Bh += (long long)ob*bOut + (long long)oi*bIn;
    Bl += (long long)ob*bOut + (long long)oi*bIn;
    const long long coff = (long long)ob*cOut + (long long)oi*cIn;
    if (EPI == 0) Cf += coff; else { Ch += coff; if (Cl) Cl += coff; }

    const int rowBase = blockIdx.y * BM;
    const int colBase = blockIdx.x * BN;

    float acc[MI][NI][4];
#pragma unroll
    for (int mi = 0; mi < MI; mi++)
#pragma unroll
        for (int ni = 0; ni < NI; ni++)
#pragma unroll
            for (int i = 0; i < 4; i++) acc[mi][ni][i] = 0.f;

    auto load_stage = [&](int s, int k0) {
        hf* st = sm + s * SST;
#pragma unroll
        for (int i = 0; i < ITER; i++) {
            int idx = i * 256 + tid;
            if (idx < CHA) {
                int r = idx >> 2, c = idx & 3;
                cp16(st + r*BKP + c*8, Ah + (size_t)(rowBase + r)*lda + k0 + c*8);
            } else {
                int j = idx - CHA;
                int half = j / (BN * 4);
                int r    = (j >> 2) % BN;
                int c    = j & 3;
                const hf* src = (half ? Bl : Bh) + (size_t)(colBase + r)*ldb + k0 + c*8;
                cp16(st + ASZ + half*BSZ + r*BKP + c*8, src);
            }
        }
    };

    const int T = K / BK;
    load_stage(0, 0);
    CP_COMMIT();

    for (int t = 0; t < T; t++) {
        if (t + 1 < T) {
            load_stage((t + 1) & 1, (t + 1) * BK);
            CP_COMMIT();
            CP_WAIT(1);
        } else {
            CP_WAIT(0);
        }
        __syncthreads();

        const hf* sA  = sm + (t & 1) * SST;
        const hf* sBh = sA + ASZ;
        const hf* sBl = sBh + BSZ;

#pragma unroll
        for (int kk = 0; kk < BK; kk += 16) {
            uint32_t ah[MI][4];
#pragma unroll
            for (int mi = 0; mi < MI; mi++) {
                int r0 = wm + mi*16 + g;
                int c0 = kk + t4*2;
                ah[mi][0] = *(const uint32_t*)&sA[(r0  )*BKP + c0    ];
                ah[mi][1] = *(const uint32_t*)&sA[(r0+8)*BKP + c0    ];
                ah[mi][2] = *(const uint32_t*)&sA[(r0  )*BKP + c0 + 8];
                ah[mi][3] = *(const uint32_t*)&sA[(r0+8)*BKP + c0 + 8];
            }
            uint32_t bh[NI][2], bl[NI][2];
#pragma unroll
            for (int ni = 0; ni < NI; ni++) {
                int rn = wn + ni*8 + g;
                int ck = kk + t4*2;
                bh[ni][0] = *(const uint32_t*)&sBh[rn*BKP + ck    ];
                bh[ni][1] = *(const uint32_t*)&sBh[rn*BKP + ck + 8];
                bl[ni][0] = *(const uint32_t*)&sBl[rn*BKP + ck    ];
                bl[ni][1] = *(const uint32_t*)&sBl[rn*BKP + ck + 8];
            }
#pragma unroll
            for (int mi = 0; mi < MI; mi++)
#pragma unroll
                for (int ni = 0; ni < NI; ni++) {
                    mma16816(acc[mi][ni], ah[mi], bh[ni]);
                    mma16816(acc[mi][ni], ah[mi], bl[ni]);
                }
        }
        __syncthreads();
    }

#pragma unroll
    for (int ni = 0; ni < NI; ni++) {
        int col = colBase + wn + ni*8 + t4*2;
        float b0 = 0.f, b1 = 0.f;
        if (bias) { b0 = __ldg(bias + col); b1 = __ldg(bias + col + 1); }
#pragma unroll
        for (int mi = 0; mi < MI; mi++) {
            int row0 = rowBase + wm + mi*16 + g;
            float v0 = acc[mi][ni][0] * alpha + b0;
            float v1 = acc[mi][ni][1] * alpha + b1;
            float v2 = acc[mi][ni][2] * alpha + b0;
            float v3 = acc[mi][ni][3] * alpha + b1;
            if (EPI == 2) {
                v0 = fmaxf(v0, 0.f); v1 = fmaxf(v1, 0.f);
                v2 = fmaxf(v2, 0.f); v3 = fmaxf(v3, 0.f);
            }
            if (EPI == 0) {
                float2 r01; r01.x = v0; r01.y = v1;
                float2 r23; r23.x = v2; r23.y = v3;
                *(float2*)(Cf + (size_t)row0     * ldc + col) = r01;
                *(float2*)(Cf + (size_t)(row0+8) * ldc + col) = r23;
            } else {
                hf h0,l0,h1,l1,h2,l2,h3,l3;
                fsplit(v0,h0,l0); fsplit(v1,h1,l1);
                fsplit(v2,h2,l2); fsplit(v3,h3,l3);
                *(uint32_t*)(Ch + (size_t)row0     * ldc + col) = pack2(h0,h1);
                *(uint32_t*)(Ch + (size_t)(row0+8) * ldc + col) = pack2(h2,h3);
                if (Cl) {
                    *(uint32_t*)(Cl + (size_t)row0     * ldc + col) = pack2(l0,l1);
                    *(uint32_t*)(Cl + (size_t)(row0+8) * ldc + col) = pack2(l2,l3);
                }
            }
        }
    }
}

// ---------------- fused flash attention (fp16x2) ------------------------------
__global__ void __launch_bounds__(256)
flash_attn(const hf* __restrict__ qh,
           const hf* __restrict__ kh, const hf* __restrict__ kl,
           const hf* __restrict__ vth, const hf* __restrict__ vtl,
           hf* __restrict__ ch)
{
    constexpr int KP = 72, VP = 136;
    constexpr int SKH = 128*KP;
    constexpr int SVH = 64*VP;
    constexpr int STG = 2*SKH + 2*SVH;

    extern __shared__ hf sm[];

    const int tid = threadIdx.x, warp = tid >> 5, lane = tid & 31;
    const int g = lane >> 2, t4 = lane & 3;
    const int wm = warp * 16;

    const int z = blockIdx.y;
    const int b = z / HEADS, h = z - b*HEADS;
    const int hc = h * HDIM;
    const int qRow = b*SEQ + blockIdx.x*128;
    const int kvTok0 = b*SEQ;
    const size_t vbase = (size_t)z * HDIM * SEQ;

    uint32_t qf[4][4];
#pragma unroll
    for (int ks = 0; ks < 4; ks++) {
        size_t a0 = (size_t)(qRow + wm + g)*EMBED + hc + ks*16 + t4*2;
        qf[ks][0] = *(const uint32_t*)(qh + a0);
        qf[ks][1] = *(const uint32_t*)(qh + a0 + 8*EMBED);
        qf[ks][2] = *(const uint32_t*)(qh + a0 + 8);
        qf[ks][3] = *(const uint32_t*)(qh + a0 + 8*EMBED + 8);
    }

    float oacc[8][4];
#pragma unroll
    for (int ni = 0; ni < 8; ni++)
#pragma unroll
        for (int j = 0; j < 4; j++) oacc[ni][j] = 0.f;
    float m0 = -1e30f, m1 = -1e30f, l0 = 0.f, l1 = 0.f;

    auto load_stage = [&](int s, int kt) {
        hf* st = sm + s * STG;
        const int kvB = kvTok0 + kt*128;
#pragma unroll
        for (int i = 0; i < 16; i++) {
            int idx = i*256 + tid;
            if (idx < 2048) {
                int half = idx >> 10, r = (idx >> 3) & 127, c = idx & 7;
                const hf* src = (half ? kl : kh) + (size_t)(kvB + r)*EMBED + hc + c*8;
                cp16(st + half*SKH + r*KP + c*8, src);
            } else {
                int j = idx - 2048;
                int half = j >> 10, r = (j >> 4) & 63, c = j & 15;
                const hf* src = (half ? vtl : vth) + vbase + (size_t)r*SEQ + kt*128 + c*8;
                cp16(st + 2*SKH + half*SVH + r*VP + c*8, src);
            }
        }
    };

    load_stage(0, 0);
    CP_COMMIT();

    for (int kt = 0; kt < SEQ/128; kt++) {
        if (kt + 1 < SEQ/128) { load_stage((kt+1)&1, kt+1); CP_COMMIT(); CP_WAIT(1); }
        else CP_WAIT(0);
        __syncthreads();

        const hf* sKh = sm + (kt & 1) * STG;
        const hf* sKl = sKh + SKH;
        const hf* sVh = sKl + SKH;
        const hf* sVl = sVh + SVH;

        float sacc[16][4];
#pragma unroll
        for (int ni = 0; ni < 16; ni++)
#pragma unroll
            for (int j = 0; j < 4; j++) sacc[ni][j] = 0.f;

#pragma unroll
        for (int ks = 0; ks < 4; ks++) {
            const int ck = ks*16 + t4*2;
#pragma unroll
            for (int ni = 0; ni < 16; ni++) {
                const int rn = ni*8 + g;
                uint32_t bh[2], bl[2];
                bh[0] = *(const uint32_t*)&sKh[rn*KP + ck];
                bh[1] = *(const uint32_t*)&sKh[rn*KP + ck + 8];
                bl[0] = *(const uint32_t*)&sKl[rn*KP + ck];
                bl[1] = *(const uint32_t*)&sKl[rn*KP + ck + 8];
                mma16816(sacc[ni], qf[ks], bh);
                mma16816(sacc[ni], qf[ks], bl);
            }
        }

        float mt0 = -1e30f, mt1 = -1e30f;
#pragma unroll
        for (int ni = 0; ni < 16; ni++) {
#pragma unroll
            for (int j = 0; j < 4; j++) sacc[ni][j] *= 0.125f;
            mt0 = fmaxf(mt0, fmaxf(sacc[ni][0], sacc[ni][1]));
            mt1 = fmaxf(mt1, fmaxf(sacc[ni][2], sacc[ni][3]));
        }
        mt0 = fmaxf(mt0, __shfl_xor_sync(~0u, mt0, 1));
        mt0 = fmaxf(mt0, __shfl_xor_sync(~0u, mt0, 2));
        mt1 = fmaxf(mt1, __shfl_xor_sync(~0u, mt1, 1));
        mt1 = fmaxf(mt1, __shfl_xor_sync(~0u, mt1, 2));

        const float mn0 = fmaxf(m0, mt0), mn1 = fmaxf(m1, mt1);
        const float sc0 = __expf(m0 - mn0), sc1 = __expf(m1 - mn1);

        float ls0 = 0.f, ls1 = 0.f;
#pragma unroll
        for (int ni = 0; ni < 16; ni++) {
            sacc[ni][0] = __expf(sacc[ni][0] - mn0);
            sacc[ni][1] = __expf(sacc[ni][1] - mn0);
            sacc[ni][2] = __expf(sacc[ni][2] - mn1);
            sacc[ni][3] = __expf(sacc[ni][3] - mn1);
            ls0 += sacc[ni][0] + sacc[ni][1];
            ls1 += sacc[ni][2] + sacc[ni][3];
        }
        ls0 += __shfl_xor_sync(~0u, ls0, 1); ls0 += __shfl_xor_sync(~0u, ls0, 2);
        ls1 += __shfl_xor_sync(~0u, ls1, 1); ls1 += __shfl_xor_sync(~0u, ls1, 2);

        l0 = l0*sc0 + ls0; l1 = l1*sc1 + ls1;
        m0 = mn0; m1 = mn1;
#pragma unroll
        for (int ni = 0; ni < 8; ni++) {
            oacc[ni][0] *= sc0; oacc[ni][1] *= sc0;
            oacc[ni][2] *= sc1; oacc[ni][3] *= sc1;
        }

        // pack P into fp16 A-fragments (hi only)
        uint32_t pf[8][4];
#pragma unroll
        for (int k2 = 0; k2 < 8; k2++) {
            const float* cA = sacc[2*k2];
            const float* cB = sacc[2*k2 + 1];
            pf[k2][0] = pack2(__float2half_rn(cA[0]), __float2half_rn(cA[1]));
            pf[k2][1] = pack2(__float2half_rn(cA[2]), __float2half_rn(cA[3]));
            pf[k2][2] = pack2(__float2half_rn(cB[0]), __float2half_rn(cB[1]));
            pf[k2][3] = pack2(__float2half_rn(cB[2]), __float2half_rn(cB[3]));
        }

#pragma unroll
        for (int ni = 0; ni < 8; ni++) {
            const int vn = ni*8 + g;
#pragma unroll
            for (int k2 = 0; k2 < 8; k2++) {
                const int ck2 = k2*16 + t4*2;
                uint32_t vbh[2], vbl[2];
                vbh[0] = *(const uint32_t*)&sVh[vn*VP + ck2];
                vbh[1] = *(const uint32_t*)&sVh[vn*VP + ck2 + 8];
                vbl[0] = *(const uint32_t*)&sVl[vn*VP + ck2];
                vbl[1] = *(const uint32_t*)&sVl[vn*VP + ck2 + 8];
                mma16816(oacc[ni], pf[k2], vbh);
                mma16816(oacc[ni], pf[k2], vbl);
            }
        }
        __syncthreads();
    }

    const float i0 = 1.f / l0, i1 = 1.f / l1;
#pragma unroll
    for (int ni = 0; ni < 8; ni++) {
        const int col = hc + ni*8 + t4*2;
        const size_t r0 = (size_t)(qRow + wm + g)*EMBED + col;
        const size_t r1 = r0 + 8*EMBED;
        *(uint32_t*)(ch + r0) = pack2(__float2half_rn(oacc[ni][0]*i0),
                                      __float2half_rn(oacc[ni][1]*i0));
        *(uint32_t*)(ch + r1) = pack2(__float2half_rn(oacc[ni][2]*i1),
                                      __float2half_rn(oacc[ni][3]*i1));
    }
}

// ---------------- split fp32 -> fp16 hi (no lo needed for A-side) -------------
__global__ void __launch_bounds__(256) tohalf_fp32(const float* __restrict__ in,
                                                   hf* __restrict__ oh, int n4)
{
    int i = blockIdx.x*256 + threadIdx.x;
    if (i >= n4) return;
    float4 v = ((const float4*)in)[i];
    uint2 uh;
    uh.x = pack2(__float2half_rn(v.x), __float2half_rn(v.y));
    uh.y = pack2(__float2half_rn(v.z), __float2half_rn(v.w));
    ((uint2*)oh)[i] = uh;
}

// ---------------- batched transpose+split fp32[R,C] -> fp16 hi/lo [C,R] -------
__global__ void __launch_bounds__(256)
transpose_split(const float* __restrict__ in, long long inOuter, long long inInner,
                int innerB, int ldi,
                hf* __restrict__ oh, hf* __restrict__ ol,
                long long outStride, int ldo)
{
    __shared__ float tile[32][33];
    const int z = blockIdx.z;
    const float* src = in + (long long)(z/innerB)*inOuter + (long long)(z%innerB)*inInner;
    hf* dh = oh + (long long)z*outStride;
    hf* dl = ol + (long long)z*outStride;
    const int c0 = blockIdx.x*32, r0 = blockIdx.y*32;
    const int tx = threadIdx.x & 31, ty = threadIdx.x >> 5;
#pragma unroll
    for (int i = 0; i < 4; i++)
        tile[ty + i*8][tx] = src[(long long)(r0 + ty + i*8)*ldi + c0 + tx];
    __syncthreads();
#pragma unroll
    for (int i = 0; i < 4; i++) {
        hf h, l; fsplit(tile[tx][ty + i*8], h, l);
        long long o = (long long)(c0 + ty + i*8)*ldo + r0 + tx;
        dh[o] = h; dl[o] = l;
    }
}

// ---------------- residual + LayerNorm (optional fp16 out) --------------------
template<bool SPLIT>
__global__ void __launch_bounds__(256)
add_ln(const float* __restrict__ X, const float* __restrict__ Y,
       const float* __restrict__ gamma, const float* __restrict__ beta,
       float* __restrict__ O, hf* __restrict__ Oh)
{
    const size_t base = (size_t)blockIdx.x * EMBED;
    const int tid = threadIdx.x;
    float4 xv = ((const float4*)(X + base))[tid];
    float4 yv = ((const float4*)(Y + base))[tid];
    float4 r; r.x=xv.x+yv.x; r.y=xv.y+yv.y; r.z=xv.z+yv.z; r.w=xv.w+yv.w;

    float s = r.x+r.y+r.z+r.w;
    float sq = r.x*r.x+r.y*r.y+r.z*r.z+r.w*r.w;
    __shared__ float rs[8], rq[8];
#pragma unroll
    for (int o = 16; o > 0; o >>= 1) {
        s += __shfl_xor_sync(~0u, s, o);
        sq += __shfl_xor_sync(~0u, sq, o);
    }
    const int wid = tid>>5, lane = tid&31;
    if (lane == 0) { rs[wid]=s; rq[wid]=sq; }
    __syncthreads();
    s = rs[0]; sq = rq[0];
#pragma unroll
    for (int w = 1; w < 8; w++) { s += rs[w]; sq += rq[w]; }

    const float mu = s * (1.f/EMBED);
    const float var = sq * (1.f/EMBED) - mu*mu;
    const float rstd = rsqrtf(var + 1e-6f);
    float4 g = ((const float4*)gamma)[tid];
    float4 bb = ((const float4*)beta)[tid];
    float4 o;
    o.x=(r.x-mu)*rstd*g.x+bb.x; o.y=(r.y-mu)*rstd*g.y+bb.y;
    o.z=(r.z-mu)*rstd*g.z+bb.z; o.w=(r.w-mu)*rstd*g.w+bb.w;
    ((float4*)(O + base))[tid] = o;
    if (SPLIT) {
        uint2 uh;
        uh.x = pack2(__float2half_rn(o.x), __float2half_rn(o.y));
        uh.y = pack2(__float2half_rn(o.z), __float2half_rn(o.w));
        ((uint2*)(Oh + base))[tid] = uh;
    }
}

// ---------------- host --------------------------------------------------------
extern "C" void kernel_launch(void* const* d_in, const int* in_sizes, int n_in,
                              void* d_out, int out_size)
{
    const float* x  = (const float*)d_in[0];
    const float* Wq = (const float*)d_in[1];  const float* bq = (const float*)d_in[2];
    const float* Wk = (const float*)d_in[3];  const float* bk = (const float*)d_in[4];
    const float* Wv = (const float*)d_in[5];  const float* bv = (const float*)d_in[6];
    const float* Wo = (const float*)d_in[7];  const float* bo = (const float*)d_in[8];
    const float* g1 = (const float*)d_in[9];  const float* be1 = (const float*)d_in[10];
    const float* W1 = (const float*)d_in[11]; const float* b1 = (const float*)d_in[12];
    const float* W2 = (const float*)d_in[13]; const float* b2 = (const float*)d_in[14];
    const float* g2 = (const float*)d_in[15]; const float* be2 = (const float*)d_in[16];
    float* out = (float*)d_out;

    float *v, *tmp, *x1;
    hf *xh,*qh,*kh,*kl,*vth,*vtl,*ch,*x1h,*hh,*wth,*wtl;
    cudaGetSymbolAddress((void**)&v,   g_v);
    cudaGetSymbolAddress((void**)&tmp, g_tmp);
    cudaGetSymbolAddress((void**)&x1,  g_x1);
    cudaGetSymbolAddress((void**)&xh,  g_x_hi);
    cudaGetSymbolAddress((void**)&qh,  g_q_hi);
    cudaGetSymbolAddress((void**)&kh,  g_k_hi);  cudaGetSymbolAddress((void**)&kl,  g_k_lo);
    cudaGetSymbolAddress((void**)&vth, g_vt_hi); cudaGetSymbolAddress((void**)&vtl, g_vt_lo);
    cudaGetSymbolAddress((void**)&ch,  g_c_hi);
    cudaGetSymbolAddress((void**)&x1h, g_x1_hi);
    cudaGetSymbolAddress((void**)&hh,  g_h_hi);
    cudaGetSymbolAddress((void**)&wth, g_wT_hi); cudaGetSymbolAddress((void**)&wtl, g_wT_lo);

    constexpr int SM128 = 2 * ((128*40) + 2*(128*40)) * 2;     // 61440 B
    constexpr int FASM  = (2*(128*72) + 2*(64*136)) * 2 * 2;   // 143360 B
    cudaFuncSetAttribute(bgemm<128,0>, cudaFuncAttributeMaxDynamicSharedMemorySize, SM128);
    cudaFuncSetAttribute(bgemm<128,1>, cudaFuncAttributeMaxDynamicSharedMemorySize, SM128);
    cudaFuncSetAttribute(bgemm<128,2>, cudaFuncAttributeMaxDynamicSharedMemorySize, SM128);
    cudaFuncSetAttribute(flash_attn,   cudaFuncAttributeMaxDynamicSharedMemorySize, FASM);

    const long long SE = (long long)SEQ*EMBED;

    // prep: x -> fp16; weights transpose+split to [out][in] hi/lo
    tohalf_fp32<<<NTOK*EMBED/4/256, 256>>>(x, xh, NTOK*EMBED/4);
    transpose_split<<<dim3(32,32,1),  256>>>(Wq, 0,0,1, EMBED, wth+OFF_WQ, wtl+OFF_WQ, 0, EMBED);
    transpose_split<<<dim3(32,32,1),  256>>>(Wk, 0,0,1, EMBED, wth+OFF_WK, wtl+OFF_WK, 0, EMBED);
    transpose_split<<<dim3(32,32,1),  256>>>(Wv, 0,0,1, EMBED, wth+OFF_WV, wtl+OFF_WV, 0, EMBED);
    transpose_split<<<dim3(32,32,1),  256>>>(Wo, 0,0,1, EMBED, wth+OFF_WO, wtl+OFF_WO, 0, EMBED);
    transpose_split<<<dim3(128,32,1), 256>>>(W1, 0,0,1, HIDDEN, wth+OFF_W1, wtl+OFF_W1, 0, EMBED);
    transpose_split<<<dim3(32,128,1), 256>>>(W2, 0,0,1, EMBED,  wth+OFF_W2, wtl+OFF_W2, 0, HIDDEN);

    // Q: fp16 hi only; K: hi+lo (B operand of flash); V: fp32 (transposed next)
    dim3 gP(8, 32, 1);
    bgemm<128,1><<<gP, 256, SM128>>>(xh, EMBED, 0,0, wth+OFF_WQ, wtl+OFF_WQ, EMBED, 0,0,
                                     nullptr, qh, nullptr, EMBED, 0,0, bq, 1.f, EMBED, 1);
    bgemm<128,1><<<gP, 256, SM128>>>(xh, EMBED, 0,0, wth+OFF_WK, wtl+OFF_WK, EMBED, 0,0,
                                     nullptr, kh, kl, EMBED, 0,0, bk, 1.f, EMBED, 1);
    bgemm<128,0><<<gP, 256, SM128>>>(xh, EMBED, 0,0, wth+OFF_WV, wtl+OFF_WV, EMBED, 0,0,
                                     v, nullptr, nullptr, EMBED, 0,0, bv, 1.f, EMBED, 1);

    // V^T per head: [64][2048] hi/lo
    transpose_split<<<dim3(2,64,NBH), 256>>>(v, SE, HDIM, HEADS, EMBED,
                                             vth, vtl, (long long)HDIM*SEQ, SEQ);

    // fused attention -> ctx (fp16)
    flash_attn<<<dim3(SEQ/128, NBH), 256, FASM>>>(qh, kh, kl, vth, vtl, ch);

    // attn_out = ctx @ Wo + bo (fp32)
    bgemm<128,0><<<gP, 256, SM128>>>(ch, EMBED, 0,0, wth+OFF_WO, wtl+OFF_WO, EMBED, 0,0,
                                     tmp, nullptr, nullptr, EMBED, 0,0, bo, 1.f, EMBED, 1);

    add_ln<true><<<NTOK, 256>>>(x, tmp, g1, be1, x1, x1h);

    // h = relu(x1 @ W1 + b1): fp16 hi only
    dim3 gF(32, 32, 1);
    bgemm<128,2><<<gF, 256, SM128>>>(x1h, EMBED, 0,0, wth+OFF_W1, wtl+OFF_W1, EMBED, 0,0,
                                     nullptr, hh, nullptr, HIDDEN, 0,0, b1, 1.f, EMBED, 1);

    // f2 = h @ W2 + b2 (fp32)
    bgemm<128,0><<<gP, 256, SM128>>>(hh, HIDDEN, 0,0, wth+OFF_W2, wtl+OFF_W2, HIDDEN, 0,0,
                                     tmp, nullptr, nullptr, EMBED, 0,0, b2, 1.f, HIDDEN, 1);

    add_ln<false><<<NTOK, 256>>>(x1, tmp, g2, be2, out, nullptr);
}

// round 7
// speedup vs baseline: 6.8959x; 1.6115x over previous
#include <cuda_runtime.h>
#include <cuda_fp16.h>
#include <cstdint>

#define EMBED  1024
#define HEADS  16
#define HDIM   64
#define HIDDEN 4096
#define SEQ    2048
#define BATCH  2
#define NTOK   (BATCH*SEQ)
#define NBH    (BATCH*HEADS)

typedef __half hf;

// ---------------- static scratch --------------------------------------------
__device__ hf    g_x_hi[NTOK*EMBED];
__device__ hf    g_q_hi[NTOK*EMBED];
__device__ hf    g_k_hi[NTOK*EMBED];
__device__ float g_v[NTOK*EMBED];
__device__ hf    g_vt_hi[NTOK*EMBED];                 // [b,h][64][2048]
__device__ hf    g_c_hi[NTOK*EMBED];
__device__ float g_tmp[NTOK*EMBED];
__device__ float g_x1[NTOK*EMBED];
__device__ hf    g_x1_hi[NTOK*EMBED];
__device__ hf    g_h_hi[(size_t)NTOK*HIDDEN];
__device__ hf    g_wT_hi[12*1024*1024];
#define OFF_WQ 0
#define OFF_WK (1*1024*1024)
#define OFF_WV (2*1024*1024)
#define OFF_WO (3*1024*1024)
#define OFF_W1 (4*1024*1024)
#define OFF_W2 (8*1024*1024)

// ---------------- helpers ----------------------------------------------------
__device__ __forceinline__ uint32_t smem_u32(const void* p) {
    uint32_t a;
    asm("{ .reg .u64 t; cvta.to.shared.u64 t, %1; cvt.u32.u64 %0, t; }" : "=r"(a) : "l"(p));
    return a;
}
__device__ __forceinline__ void cp16(const void* smem_dst, const void* gsrc) {
    uint32_t d = smem_u32(smem_dst);
    asm volatile("cp.async.cg.shared.global [%0], [%1], 16;" :: "r"(d), "l"(gsrc) : "memory");
}
#define CP_COMMIT() asm volatile("cp.async.commit_group;" ::: "memory")
#define CP_WAIT(n)  asm volatile("cp.async.wait_group %0;" :: "n"(n) : "memory")

__device__ __forceinline__ void mma16816(float* c, const uint32_t* a, const uint32_t* b) {
    asm volatile("mma.sync.aligned.m16n8k16.row.col.f32.f16.f16.f32 "
        "{%0,%1,%2,%3}, {%4,%5,%6,%7}, {%8,%9}, {%0,%1,%2,%3};"
        : "+f"(c[0]), "+f"(c[1]), "+f"(c[2]), "+f"(c[3])
        : "r"(a[0]), "r"(a[1]), "r"(a[2]), "r"(a[3]), "r"(b[0]), "r"(b[1]));
}
__device__ __forceinline__ uint32_t pack2(hf a, hf b) {
    __half2 t; t.x = a; t.y = b; return *(uint32_t*)&t;
}

// ---------------- fp16 HMMA GEMM ----------------------------------------------
// D[M,N] = alpha*sum_k A[m,k]*B[n,k] (+bias)(+relu). A, B fp16 (hi only).
// BM=128, BK=32, double-buffered cp.async. 256 threads = 8 warps.
// EPI: 0 = fp32 out, 1 = fp16 out, 2 = relu + fp16 out
template<int BN, int EPI>
__global__ void __launch_bounds__(256)
bgemm(const hf* __restrict__ Ah, int lda, long long aOut, long long aIn,
      const hf* __restrict__ Bh, int ldb, long long bOut, long long bIn,
      float* Cf, hf* Ch, int ldc, long long cOut, long long cIn,
      const float* __restrict__ bias, float alpha, int K, int inner)
{
    constexpr int BM = 128, BK = 32, BKP = 40;
    constexpr int WM = 2, WN = 4;
    constexpr int WTM = BM / WM, WTN = BN / WN;
    constexpr int MI = WTM / 16, NI = WTN / 8;
    constexpr int ASZ = BM * BKP;
    constexpr int BSZ = BN * BKP;
    constexpr int SST = ASZ + BSZ;
    constexpr int CHA = BM * 4;
    constexpr int CHB = BN * 4;
    constexpr int ITER = (CHA + CHB) / 256;

    extern __shared__ hf sm[];

    const int tid = threadIdx.x;
    const int warp = tid >> 5, lane = tid & 31;
    const int g = lane >> 2, t4 = lane & 3;
    const int wm = (warp % WM) * WTM;
    const int wn = (warp / WM) * WTN;

    const int z = blockIdx.z, ob = z / inner, oi = z - ob*inner;
    Ah += (long long)ob*aOut + (long long)oi*aIn;
    Bh += (long long)ob*bOut + (long long)oi*bIn;
    const long long coff = (long long)ob*cOut + (long long)oi*cIn;
    if (EPI == 0) Cf += coff; else Ch += coff;

    const int rowBase = blockIdx.y * BM;
    const int colBase = blockIdx.x * BN;

    float acc[MI][NI][4];
#pragma unroll
    for (int mi = 0; mi < MI; mi++)
#pragma unroll
        for (int ni = 0; ni < NI; ni++)
#pragma unroll
            for (int i = 0; i < 4; i++) acc[mi][ni][i] = 0.f;

    auto load_stage = [&](int s, int k0) {
        hf* st = sm + s * SST;
#pragma unroll
        for (int i = 0; i < ITER; i++) {
            int idx = i * 256 + tid;
            if (idx < CHA) {
                int r = idx >> 2, c = idx & 3;
                cp16(st + r*BKP + c*8, Ah + (size_t)(rowBase + r)*lda + k0 + c*8);
            } else {
                int j = idx - CHA;
                int r = j >> 2, c = j & 3;
                cp16(st + ASZ + r*BKP + c*8, Bh + (size_t)(colBase + r)*ldb + k0 + c*8);
            }
        }
    };

    const int T = K / BK;
    load_stage(0, 0);
    CP_COMMIT();

    for (int t = 0; t < T; t++) {
        if (t + 1 < T) {
            load_stage((t + 1) & 1, (t + 1) * BK);
            CP_COMMIT();
            CP_WAIT(1);
        } else {
            CP_WAIT(0);
        }
        __syncthreads();

        const hf* sA = sm + (t & 1) * SST;
        const hf* sB = sA + ASZ;

#pragma unroll
        for (int kk = 0; kk < BK; kk += 16) {
            uint32_t ah[MI][4];
#pragma unroll
            for (int mi = 0; mi < MI; mi++) {
                int r0 = wm + mi*16 + g;
                int c0 = kk + t4*2;
                ah[mi][0] = *(const uint32_t*)&sA[(r0  )*BKP + c0    ];
                ah[mi][1] = *(const uint32_t*)&sA[(r0+8)*BKP + c0    ];
                ah[mi][2] = *(const uint32_t*)&sA[(r0  )*BKP + c0 + 8];
                ah[mi][3] = *(const uint32_t*)&sA[(r0+8)*BKP + c0 + 8];
            }
            uint32_t bh[NI][2];
#pragma unroll
            for (int ni = 0; ni < NI; ni++) {
                int rn = wn + ni*8 + g;
                int ck = kk + t4*2;
                bh[ni][0] = *(const uint32_t*)&sB[rn*BKP + ck    ];
                bh[ni][1] = *(const uint32_t*)&sB[rn*BKP + ck + 8];
            }
#pragma unroll
            for (int mi = 0; mi < MI; mi++)
#pragma unroll
                for (int ni = 0; ni < NI; ni++)
                    mma16816(acc[mi][ni], ah[mi], bh[ni]);
        }
        __syncthreads();
    }

#pragma unroll
    for (int ni = 0; ni < NI; ni++) {
        int col = colBase + wn + ni*8 + t4*2;
        float b0 = 0.f, b1 = 0.f;
        if (bias) { b0 = __ldg(bias + col); b1 = __ldg(bias + col + 1); }
#pragma unroll
        for (int mi = 0; mi < MI; mi++) {
            int row0 = rowBase + wm + mi*16 + g;
            float v0 = acc[mi][ni][0] * alpha + b0;
            float v1 = acc[mi][ni][1] * alpha + b1;
            float v2 = acc[mi][ni][2] * alpha + b0;
            float v3 = acc[mi][ni][3] * alpha + b1;
            if (EPI == 2) {
                v0 = fmaxf(v0, 0.f); v1 = fmaxf(v1, 0.f);
                v2 = fmaxf(v2, 0.f); v3 = fmaxf(v3, 0.f);
            }
            if (EPI == 0) {
                float2 r01; r01.x = v0; r01.y = v1;
                float2 r23; r23.x = v2; r23.y = v3;
                *(float2*)(Cf + (size_t)row0     * ldc + col) = r01;
                *(float2*)(Cf + (size_t)(row0+8) * ldc + col) = r23;
            } else {
                *(uint32_t*)(Ch + (size_t)row0     * ldc + col) =
                    pack2(__float2half_rn(v0), __float2half_rn(v1));
                *(uint32_t*)(Ch + (size_t)(row0+8) * ldc + col) =
                    pack2(__float2half_rn(v2), __float2half_rn(v3));
            }
        }
    }
}

// ---------------- fused flash attention (fp16) --------------------------------
__global__ void __launch_bounds__(256)
flash_attn(const hf* __restrict__ qh,
           const hf* __restrict__ kh,
           const hf* __restrict__ vth,
           hf* __restrict__ ch)
{
    constexpr int KP = 72, VP = 136;
    constexpr int SKH = 128*KP;
    constexpr int SVH = 64*VP;
    constexpr int STG = SKH + SVH;

    extern __shared__ hf sm[];

    const int tid = threadIdx.x, warp = tid >> 5, lane = tid & 31;
    const int g = lane >> 2, t4 = lane & 3;
    const int wm = warp * 16;

    const int z = blockIdx.y;
    const int b = z / HEADS, h = z - b*HEADS;
    const int hc = h * HDIM;
    const int qRow = b*SEQ + blockIdx.x*128;
    const int kvTok0 = b*SEQ;
    const size_t vbase = (size_t)z * HDIM * SEQ;

    uint32_t qf[4][4];
#pragma unroll
    for (int ks = 0; ks < 4; ks++) {
        size_t a0 = (size_t)(qRow + wm + g)*EMBED + hc + ks*16 + t4*2;
        qf[ks][0] = *(const uint32_t*)(qh + a0);
        qf[ks][1] = *(const uint32_t*)(qh + a0 + 8*EMBED);
        qf[ks][2] = *(const uint32_t*)(qh + a0 + 8);
        qf[ks][3] = *(const uint32_t*)(qh + a0 + 8*EMBED + 8);
    }

    float oacc[8][4];
#pragma unroll
    for (int ni = 0; ni < 8; ni++)
#pragma unroll
        for (int j = 0; j < 4; j++) oacc[ni][j] = 0.f;
    float m0 = -1e30f, m1 = -1e30f, l0 = 0.f, l1 = 0.f;

    auto load_stage = [&](int s, int kt) {
        hf* st = sm + s * STG;
        const int kvB = kvTok0 + kt*128;
#pragma unroll
        for (int i = 0; i < 8; i++) {
            int idx = i*256 + tid;
            if (idx < 1024) {                                  // K tile: 128 x 64
                int r = idx >> 3, c = idx & 7;
                cp16(st + r*KP + c*8, kh + (size_t)(kvB + r)*EMBED + hc + c*8);
            } else {                                           // V^T tile: 64 x 128
                int j = idx - 1024;
                int r = j >> 4, c = j & 15;
                cp16(st + SKH + r*VP + c*8, vth + vbase + (size_t)r*SEQ + kt*128 + c*8);
            }
        }
    };

    load_stage(0, 0);
    CP_COMMIT();

    for (int kt = 0; kt < SEQ/128; kt++) {
        if (kt + 1 < SEQ/128) { load_stage((kt+1)&1, kt+1); CP_COMMIT(); CP_WAIT(1); }
        else CP_WAIT(0);
        __syncthreads();

        const hf* sK = sm + (kt & 1) * STG;
        const hf* sV = sK + SKH;

        float sacc[16][4];
#pragma unroll
        for (int ni = 0; ni < 16; ni++)
#pragma unroll
            for (int j = 0; j < 4; j++) sacc[ni][j] = 0.f;

#pragma unroll
        for (int ks = 0; ks < 4; ks++) {
            const int ck = ks*16 + t4*2;
#pragma unroll
            for (int ni = 0; ni < 16; ni++) {
                const int rn = ni*8 + g;
                uint32_t bh[2];
                bh[0] = *(const uint32_t*)&sK[rn*KP + ck];
                bh[1] = *(const uint32_t*)&sK[rn*KP + ck + 8];
                mma16816(sacc[ni], qf[ks], bh);
            }
        }

        float mt0 = -1e30f, mt1 = -1e30f;
#pragma unroll
        for (int ni = 0; ni < 16; ni++) {
#pragma unroll
            for (int j = 0; j < 4; j++) sacc[ni][j] *= 0.125f;
            mt0 = fmaxf(mt0, fmaxf(sacc[ni][0], sacc[ni][1]));
            mt1 = fmaxf(mt1, fmaxf(sacc[ni][2], sacc[ni][3]));
        }
        mt0 = fmaxf(mt0, __shfl_xor_sync(~0u, mt0, 1));
        mt0 = fmaxf(mt0, __shfl_xor_sync(~0u, mt0, 2));
        mt1 = fmaxf(mt1, __shfl_xor_sync(~0u, mt1, 1));
        mt1 = fmaxf(mt1, __shfl_xor_sync(~0u, mt1, 2));

        const float mn0 = fmaxf(m0, mt0), mn1 = fmaxf(m1, mt1);
        const float sc0 = __expf(m0 - mn0), sc1 = __expf(m1 - mn1);

        float ls0 = 0.f, ls1 = 0.f;
#pragma unroll
        for (int ni = 0; ni < 16; ni++) {
            sacc[ni][0] = __expf(sacc[ni][0] - mn0);
            sacc[ni][1] = __expf(sacc[ni][1] - mn0);
            sacc[ni][2] = __expf(sacc[ni][2] - mn1);
            sacc[ni][3] = __expf(sacc[ni][3] - mn1);
            ls0 += sacc[ni][0] + sacc[ni][1];
            ls1 += sacc[ni][2] + sacc[ni][3];
        }
        ls0 += __shfl_xor_sync(~0u, ls0, 1); ls0 += __shfl_xor_sync(~0u, ls0, 2);
        ls1 += __shfl_xor_sync(~0u, ls1, 1); ls1 += __shfl_xor_sync(~0u, ls1, 2);

        l0 = l0*sc0 + ls0; l1 = l1*sc1 + ls1;
        m0 = mn0; m1 = mn1;
#pragma unroll
        for (int ni = 0; ni < 8; ni++) {
            oacc[ni][0] *= sc0; oacc[ni][1] *= sc0;
            oacc[ni][2] *= sc1; oacc[ni][3] *= sc1;
        }

        uint32_t pf[8][4];
#pragma unroll
        for (int k2 = 0; k2 < 8; k2++) {
            const float* cA = sacc[2*k2];
            const float* cB = sacc[2*k2 + 1];
            pf[k2][0] = pack2(__float2half_rn(cA[0]), __float2half_rn(cA[1]));
            pf[k2][1] = pack2(__float2half_rn(cA[2]), __float2half_rn(cA[3]));
            pf[k2][2] = pack2(__float2half_rn(cB[0]), __float2half_rn(cB[1]));
            pf[k2][3] = pack2(__float2half_rn(cB[2]), __float2half_rn(cB[3]));
        }

#pragma unroll
        for (int ni = 0; ni < 8; ni++) {
            const int vn = ni*8 + g;
#pragma unroll
            for (int k2 = 0; k2 < 8; k2++) {
                const int ck2 = k2*16 + t4*2;
                uint32_t vb[2];
                vb[0] = *(const uint32_t*)&sV[vn*VP + ck2];
                vb[1] = *(const uint32_t*)&sV[vn*VP + ck2 + 8];
                mma16816(oacc[ni], pf[k2], vb);
            }
        }
        __syncthreads();
    }

    const float i0 = 1.f / l0, i1 = 1.f / l1;
#pragma unroll
    for (int ni = 0; ni < 8; ni++) {
        const int col = hc + ni*8 + t4*2;
        const size_t r0 = (size_t)(qRow + wm + g)*EMBED + col;
        const size_t r1 = r0 + 8*EMBED;
        *(uint32_t*)(ch + r0) = pack2(__float2half_rn(oacc[ni][0]*i0),
                                      __float2half_rn(oacc[ni][1]*i0));
        *(uint32_t*)(ch + r1) = pack2(__float2half_rn(oacc[ni][2]*i1),
                                      __float2half_rn(oacc[ni][3]*i1));
    }
}

// ---------------- fp32 -> fp16 ------------------------------------------------
__global__ void __launch_bounds__(256) tohalf_fp32(const float* __restrict__ in,
                                                   hf* __restrict__ oh, int n4)
{
    int i = blockIdx.x*256 + threadIdx.x;
    if (i >= n4) return;
    float4 v = ((const float4*)in)[i];
    uint2 uh;
    uh.x = pack2(__float2half_rn(v.x), __float2half_rn(v.y));
    uh.y = pack2(__float2half_rn(v.z), __float2half_rn(v.w));
    ((uint2*)oh)[i] = uh;
}

// ---------------- batched transpose fp32[R,C] -> fp16 [C,R] --------------------
__global__ void __launch_bounds__(256)
transpose_half(const float* __restrict__ in, long long inOuter, long long inInner,
               int innerB, int ldi,
               hf* __restrict__ oh, long long outStride, int ldo)
{
    __shared__ float tile[32][33];
    const int z = blockIdx.z;
    const float* src = in + (long long)(z/innerB)*inOuter + (long long)(z%innerB)*inInner;
    hf* dh = oh + (long long)z*outStride;
    const int c0 = blockIdx.x*32, r0 = blockIdx.y*32;
    const int tx = threadIdx.x & 31, ty = threadIdx.x >> 5;
#pragma unroll
    for (int i = 0; i < 4; i++)
        tile[ty + i*8][tx] = src[(long long)(r0 + ty + i*8)*ldi + c0 + tx];
    __syncthreads();
#pragma unroll
    for (int i = 0; i < 4; i++)
        dh[(long long)(c0 + ty + i*8)*ldo + r0 + tx] = __float2half_rn(tile[tx][ty + i*8]);
}

// ---------------- residual + LayerNorm (optional fp16 out) --------------------
template<bool SPLIT>
__global__ void __launch_bounds__(256)
add_ln(const float* __restrict__ X, const float* __restrict__ Y,
       const float* __restrict__ gamma, const float* __restrict__ beta,
       float* __restrict__ O, hf* __restrict__ Oh)
{
    const size_t base = (size_t)blockIdx.x * EMBED;
    const int tid = threadIdx.x;
    float4 xv = ((const float4*)(X + base))[tid];
    float4 yv = ((const float4*)(Y + base))[tid];
    float4 r; r.x=xv.x+yv.x; r.y=xv.y+yv.y; r.z=xv.z+yv.z; r.w=xv.w+yv.w;

    float s = r.x+r.y+r.z+r.w;
    float sq = r.x*r.x+r.y*r.y+r.z*r.z+r.w*r.w;
    __shared__ float rs[8], rq[8];
#pragma unroll
    for (int o = 16; o > 0; o >>= 1) {
        s += __shfl_xor_sync(~0u, s, o);
        sq += __shfl_xor_sync(~0u, sq, o);
    }
    const int wid = tid>>5, lane = tid&31;
    if (lane == 0) { rs[wid]=s; rq[wid]=sq; }
    __syncthreads();
    s = rs[0]; sq = rq[0];
#pragma unroll
    for (int w = 1; w < 8; w++) { s += rs[w]; sq += rq[w]; }

    const float mu = s * (1.f/EMBED);
    const float var = sq * (1.f/EMBED) - mu*mu;
    const float rstd = rsqrtf(var + 1e-6f);
    float4 g = ((const float4*)gamma)[tid];
    float4 bb = ((const float4*)beta)[tid];
    float4 o;
    o.x=(r.x-mu)*rstd*g.x+bb.x; o.y=(r.y-mu)*rstd*g.y+bb.y;
    o.z=(r.z-mu)*rstd*g.z+bb.z; o.w=(r.w-mu)*rstd*g.w+bb.w;
    ((float4*)(O + base))[tid] = o;
    if (SPLIT) {
        uint2 uh;
        uh.x = pack2(__float2half_rn(o.x), __float2half_rn(o.y));
        uh.y = pack2(__float2half_rn(o.z), __float2half_rn(o.w));
        ((uint2*)(Oh + base))[tid] = uh;
    }
}

// ---------------- host --------------------------------------------------------
extern "C" void kernel_launch(void* const* d_in, const int* in_sizes, int n_in,
                              void* d_out, int out_size)
{
    const float* x  = (const float*)d_in[0];
    const float* Wq = (const float*)d_in[1];  const float* bq = (const float*)d_in[2];
    const float* Wk = (const float*)d_in[3];  const float* bk = (const float*)d_in[4];
    const float* Wv = (const float*)d_in[5];  const float* bv = (const float*)d_in[6];
    const float* Wo = (const float*)d_in[7];  const float* bo = (const float*)d_in[8];
    const float* g1 = (const float*)d_in[9];  const float* be1 = (const float*)d_in[10];
    const float* W1 = (const float*)d_in[11]; const float* b1 = (const float*)d_in[12];
    const float* W2 = (const float*)d_in[13]; const float* b2 = (const float*)d_in[14];
    const float* g2 = (const float*)d_in[15]; const float* be2 = (const float*)d_in[16];
    float* out = (float*)d_out;

    float *v, *tmp, *x1;
    hf *xh,*qh,*kh,*vth,*ch,*x1h,*hh,*wth;
    cudaGetSymbolAddress((void**)&v,   g_v);
    cudaGetSymbolAddress((void**)&tmp, g_tmp);
    cudaGetSymbolAddress((void**)&x1,  g_x1);
    cudaGetSymbolAddress((void**)&xh,  g_x_hi);
    cudaGetSymbolAddress((void**)&qh,  g_q_hi);
    cudaGetSymbolAddress((void**)&kh,  g_k_hi);
    cudaGetSymbolAddress((void**)&vth, g_vt_hi);
    cudaGetSymbolAddress((void**)&ch,  g_c_hi);
    cudaGetSymbolAddress((void**)&x1h, g_x1_hi);
    cudaGetSymbolAddress((void**)&hh,  g_h_hi);
    cudaGetSymbolAddress((void**)&wth, g_wT_hi);

    constexpr int SM128 = 2 * ((128*40) + (128*40)) * 2;       // 40960 B
    constexpr int FASM  = (128*72 + 64*136) * 2 * 2;           // 71680 B
    cudaFuncSetAttribute(bgemm<128,0>, cudaFuncAttributeMaxDynamicSharedMemorySize, SM128);
    cudaFuncSetAttribute(bgemm<128,1>, cudaFuncAttributeMaxDynamicSharedMemorySize, SM128);
    cudaFuncSetAttribute(bgemm<128,2>, cudaFuncAttributeMaxDynamicSharedMemorySize, SM128);
    cudaFuncSetAttribute(flash_attn,   cudaFuncAttributeMaxDynamicSharedMemorySize, FASM);

    const long long SE = (long long)SEQ*EMBED;

    // prep: x -> fp16; weights transposed to [out][in] fp16
    tohalf_fp32<<<NTOK*EMBED/4/256, 256>>>(x, xh, NTOK*EMBED/4);
    transpose_half<<<dim3(32,32,1),  256>>>(Wq, 0,0,1, EMBED, wth+OFF_WQ, 0, EMBED);
    transpose_half<<<dim3(32,32,1),  256>>>(Wk, 0,0,1, EMBED, wth+OFF_WK, 0, EMBED);
    transpose_half<<<dim3(32,32,1),  256>>>(Wv, 0,0,1, EMBED, wth+OFF_WV, 0, EMBED);
    transpose_half<<<dim3(32,32,1),  256>>>(Wo, 0,0,1, EMBED, wth+OFF_WO, 0, EMBED);
    transpose_half<<<dim3(128,32,1), 256>>>(W1, 0,0,1, HIDDEN, wth+OFF_W1, 0, EMBED);
    transpose_half<<<dim3(32,128,1), 256>>>(W2, 0,0,1, EMBED,  wth+OFF_W2, 0, HIDDEN);

    // Q, K: fp16; V: fp32 (transposed next)
    dim3 gP(8, 32, 1);
    bgemm<128,1><<<gP, 256, SM128>>>(xh, EMBED, 0,0, wth+OFF_WQ, EMBED, 0,0,
                                     nullptr, qh, EMBED, 0,0, bq, 1.f, EMBED, 1);
    bgemm<128,1><<<gP, 256, SM128>>>(xh, EMBED, 0,0, wth+OFF_WK, EMBED, 0,0,
                                     nullptr, kh, EMBED, 0,0, bk, 1.f, EMBED, 1);
    bgemm<128,0><<<gP, 256, SM128>>>(xh, EMBED, 0,0, wth+OFF_WV, EMBED, 0,0,
                                     v, nullptr, EMBED, 0,0, bv, 1.f, EMBED, 1);

    // V^T per head: [64][2048] fp16
    transpose_half<<<dim3(2,64,NBH), 256>>>(v, SE, HDIM, HEADS, EMBED,
                                            vth, (long long)HDIM*SEQ, SEQ);

    // fused attention -> ctx (fp16)
    flash_attn<<<dim3(SEQ/128, NBH), 256, FASM>>>(qh, kh, vth, ch);

    // attn_out = ctx @ Wo + bo (fp32)
    bgemm<128,0><<<gP, 256, SM128>>>(ch, EMBED, 0,0, wth+OFF_WO, EMBED, 0,0,
                                     tmp, nullptr, EMBED, 0,0, bo, 1.f, EMBED, 1);

    add_ln<true><<<NTOK, 256>>>(x, tmp, g1, be1, x1, x1h);

    // h = relu(x1 @ W1 + b1): fp16
    dim3 gF(32, 32, 1);
    bgemm<128,2><<<gF, 256, SM128>>>(x1h, EMBED, 0,0, wth+OFF_W1, EMBED, 0,0,
                                     nullptr, hh, HIDDEN, 0,0, b1, 1.f, EMBED, 1);

    // f2 = h @ W2 + b2 (fp32)
    bgemm<128,0><<<gP, 256, SM128>>>(hh, HIDDEN, 0,0, wth+OFF_W2, HIDDEN, 0,0,
                                     tmp, nullptr, EMBED, 0,0, b2, 1.f, HIDDEN, 1);

    add_ln<false><<<NTOK, 256>>>(x1, tmp, g2, be2, out, nullptr);
}

// round 8
// speedup vs baseline: 8.4144x; 1.2202x over previous
#include <cuda_runtime.h>
#include <cuda_fp16.h>
#include <cstdint>

#define EMBED  1024
#define HEADS  16
#define HDIM   64
#define HIDDEN 4096
#define SEQ    2048
#define BATCH  2
#define NTOK   (BATCH*SEQ)
#define NBH    (BATCH*HEADS)

typedef __half hf;

// ---------------- static scratch --------------------------------------------
__device__ hf    g_x_hi[NTOK*EMBED];
__device__ hf    g_q_hi[NTOK*EMBED];
__device__ hf    g_k_hi[NTOK*EMBED];
__device__ hf    g_vt_hi[NTOK*EMBED];                 // [b,h][64][2048]
__device__ hf    g_c_hi[NTOK*EMBED];
__device__ float g_tmp[NTOK*EMBED];
__device__ float g_x1[NTOK*EMBED];
__device__ hf    g_x1_hi[NTOK*EMBED];
__device__ hf    g_h_hi[(size_t)NTOK*HIDDEN];
__device__ hf    g_w16[12*1024*1024];                 // fp16 weights, ORIGINAL [k][n] layout
__device__ float g_bqkv[3*EMBED];
#define OFF_WQ 0
#define OFF_WK (1*1024*1024)
#define OFF_WV (2*1024*1024)
#define OFF_WO (3*1024*1024)
#define OFF_W1 (4*1024*1024)
#define OFF_W2 (8*1024*1024)

// ---------------- helpers ----------------------------------------------------
__device__ __forceinline__ uint32_t smem_u32(const void* p) {
    uint32_t a;
    asm("{ .reg .u64 t; cvta.to.shared.u64 t, %1; cvt.u32.u64 %0, t; }" : "=r"(a) : "l"(p));
    return a;
}
__device__ __forceinline__ void cp16(const void* smem_dst, const void* gsrc) {
    uint32_t d = smem_u32(smem_dst);
    asm volatile("cp.async.cg.shared.global [%0], [%1], 16;" :: "r"(d), "l"(gsrc) : "memory");
}
#define CP_COMMIT() asm volatile("cp.async.commit_group;" ::: "memory")
#define CP_WAIT(n)  asm volatile("cp.async.wait_group %0;" :: "n"(n) : "memory")

__device__ __forceinline__ void mma16816(float* c, const uint32_t* a, const uint32_t* b) {
    asm volatile("mma.sync.aligned.m16n8k16.row.col.f32.f16.f16.f32 "
        "{%0,%1,%2,%3}, {%4,%5,%6,%7}, {%8,%9}, {%0,%1,%2,%3};"
        : "+f"(c[0]), "+f"(c[1]), "+f"(c[2]), "+f"(c[3])
        : "r"(a[0]), "r"(a[1]), "r"(a[2]), "r"(a[3]), "r"(b[0]), "r"(b[1]));
}
__device__ __forceinline__ void ldsm4(uint32_t& r0, uint32_t& r1, uint32_t& r2,
                                      uint32_t& r3, uint32_t a) {
    asm volatile("ldmatrix.sync.aligned.m8n8.x4.shared.b16 {%0,%1,%2,%3}, [%4];"
        : "=r"(r0), "=r"(r1), "=r"(r2), "=r"(r3) : "r"(a));
}
__device__ __forceinline__ void ldsm4t(uint32_t& r0, uint32_t& r1, uint32_t& r2,
                                       uint32_t& r3, uint32_t a) {
    asm volatile("ldmatrix.sync.aligned.m8n8.x4.trans.shared.b16 {%0,%1,%2,%3}, [%4];"
        : "=r"(r0), "=r"(r1), "=r"(r2), "=r"(r3) : "r"(a));
}
__device__ __forceinline__ uint32_t pack2(hf a, hf b) {
    __half2 t; t.x = a; t.y = b; return *(uint32_t*)&t;
}

// ---------------- fp16 HMMA GEMM, weights untransposed [k][n] -----------------
// D[M,N] = alpha*(A[m,k] @ B[k,n]) (+bias)(+relu/epi). BM=128, BK=32, 2 stages.
// EPI: 0 = fp32 out; 2 = relu + fp16 out; 3 = fused QKV epilogue
template<int BN, int EPI>
__global__ void __launch_bounds__(256, 2)
bgemm(const hf* __restrict__ Ah, int lda,
      const hf* __restrict__ Bh, int ldb,
      float* __restrict__ Cf, hf* __restrict__ Ch,
      hf* __restrict__ Kp, hf* __restrict__ Vt, int ldc,
      const float* __restrict__ bias, float alpha, int K)
{
    constexpr int BM = 128, BK = 32, BKP = 40, BNP = BN + 8;
    constexpr int WM = 2, WN = 4;
    constexpr int WTM = BM / WM, WTN = BN / WN;       // 64 x 32
    constexpr int MI = WTM / 16, NI = WTN / 8;        // 4, 4
    constexpr int ASZ = BM * BKP;                     // 5120
    constexpr int BSZ = BK * BNP;                     // 4352
    constexpr int SST = ASZ + BSZ;

    extern __shared__ hf sm[];
    const uint32_t smu = smem_u32(sm);

    const int tid = threadIdx.x;
    const int warp = tid >> 5, lane = tid & 31;
    const int g = lane >> 2, t4 = lane & 3;
    const int lr = lane & 7, grp = lane >> 3;
    // ldmatrix per-lane offsets
    const int aOffR = lr + ((grp & 1) << 3), aOffC = (grp >> 1) << 3;  // A [m][k]
    const int tOffR = lr + ((grp & 1) << 3), tOffC = (grp >> 1) << 3;  // B trans [k][n]
    const int wm = (warp % WM) * WTM;
    const int wn = (warp / WM) * WTN;

    const int rowBase = blockIdx.y * BM;
    const int colBase = blockIdx.x * BN;
    const int seg   = colBase >> 10;                  // EPI3 only
    const int lcol0 = colBase & 1023;

    const hf* Bbase = (EPI == 3)
        ? Bh + (size_t)seg * (1024*1024) + lcol0
        : Bh + colBase;

    float acc[MI][NI][4];
#pragma unroll
    for (int mi = 0; mi < MI; mi++)
#pragma unroll
        for (int ni = 0; ni < NI; ni++)
#pragma unroll
            for (int i = 0; i < 4; i++) acc[mi][ni][i] = 0.f;

    auto load_stage = [&](int s, int k0) {
        hf* st = sm + s * SST;
#pragma unroll
        for (int i = 0; i < 4; i++) {
            int idx = i * 256 + tid;
            if (idx < 512) {                          // A: 128 rows x 4 chunks
                int r = idx >> 2, c = idx & 3;
                cp16(st + r*BKP + c*8, Ah + (size_t)(rowBase + r)*lda + k0 + c*8);
            } else {                                  // B: 32 k-rows x 16 chunks
                int j = idx - 512;
                int r = j >> 4, c = j & 15;
                cp16(st + ASZ + r*BNP + c*8, Bbase + (size_t)(k0 + r)*ldb + c*8);
            }
        }
    };

    const int T = K / BK;
    load_stage(0, 0);
    CP_COMMIT();

    for (int t = 0; t < T; t++) {
        if (t + 1 < T) {
            load_stage((t + 1) & 1, (t + 1) * BK);
            CP_COMMIT();
            CP_WAIT(1);
        } else {
            CP_WAIT(0);
        }
        __syncthreads();

        const uint32_t sAu = smu + ((t & 1) * SST) * 2;
        const uint32_t sBu = sAu + ASZ * 2;

#pragma unroll
        for (int kk = 0; kk < BK; kk += 16) {
            uint32_t ah[MI][4];
#pragma unroll
            for (int mi = 0; mi < MI; mi++)
                ldsm4(ah[mi][0], ah[mi][1], ah[mi][2], ah[mi][3],
                      sAu + (uint32_t)((wm + mi*16 + aOffR)*BKP + kk + aOffC) * 2);
            uint32_t bh[NI][2];
#pragma unroll
            for (int p = 0; p < NI/2; p++)
                ldsm4t(bh[2*p][0], bh[2*p][1], bh[2*p+1][0], bh[2*p+1][1],
                       sBu + (uint32_t)((kk + tOffR)*BNP + wn + p*16 + tOffC) * 2);
#pragma unroll
            for (int mi = 0; mi < MI; mi++)
#pragma unroll
                for (int ni = 0; ni < NI; ni++)
                    mma16816(acc[mi][ni], ah[mi], bh[ni]);
        }
        __syncthreads();
    }

    // ---- epilogue ------------------------------------------------------------
#pragma unroll
    for (int ni = 0; ni < NI; ni++) {
        int colW = wn + ni*8 + t4*2;                  // col within block tile
        int gcol = colBase + colW;
        float b0 = 0.f, b1 = 0.f;
        if (bias) { b0 = __ldg(bias + gcol); b1 = __ldg(bias + gcol + 1); }
#pragma unroll
        for (int mi = 0; mi < MI; mi++) {
            int row0 = rowBase + wm + mi*16 + g;
            float v0 = acc[mi][ni][0] * alpha + b0;
            float v1 = acc[mi][ni][1] * alpha + b1;
            float v2 = acc[mi][ni][2] * alpha + b0;
            float v3 = acc[mi][ni][3] * alpha + b1;
            if (EPI == 2) {
                v0 = fmaxf(v0, 0.f); v1 = fmaxf(v1, 0.f);
                v2 = fmaxf(v2, 0.f); v3 = fmaxf(v3, 0.f);
            }
            if (EPI == 0) {
                float2 r01; r01.x = v0; r01.y = v1;
                float2 r23; r23.x = v2; r23.y = v3;
                *(float2*)(Cf + (size_t)row0     * ldc + gcol) = r01;
                *(float2*)(Cf + (size_t)(row0+8) * ldc + gcol) = r23;
            } else if (EPI == 2) {
                *(uint32_t*)(Ch + (size_t)row0     * ldc + gcol) =
                    pack2(__float2half_rn(v0), __float2half_rn(v1));
                *(uint32_t*)(Ch + (size_t)(row0+8) * ldc + gcol) =
                    pack2(__float2half_rn(v2), __float2half_rn(v3));
            } else {                                  // EPI 3: fused QKV
                int lcol = lcol0 + colW;
                if (seg < 2) {
                    hf* dst = seg ? Kp : Ch;
                    *(uint32_t*)(dst + (size_t)row0     * EMBED + lcol) =
                        pack2(__float2half_rn(v0), __float2half_rn(v1));
                    *(uint32_t*)(dst + (size_t)(row0+8) * EMBED + lcol) =
                        pack2(__float2half_rn(v2), __float2half_rn(v3));
                } else {                              // V -> [b,h][64][2048]
                    int head = lcol >> 6, d = lcol & 63;
                    int bb0 = row0 >> 11, t0 = row0 & 2047;
                    int bb1 = (row0+8) >> 11, t1 = (row0+8) & 2047;
                    size_t base0 = ((size_t)(bb0*HEADS + head)*64 + d)*2048;
                    size_t base1 = ((size_t)(bb1*HEADS + head)*64 + d)*2048;
                    Vt[base0 + t0]        = __float2half_rn(v0);
                    Vt[base0 + 2048 + t0] = __float2half_rn(v1);
                    Vt[base1 + t1]        = __float2half_rn(v2);
                    Vt[base1 + 2048 + t1] = __float2half_rn(v3);
                }
            }
        }
    }
}

// ---------------- fused flash attention (fp16, ldmatrix) ----------------------
__global__ void __launch_bounds__(256)
flash_attn(const hf* __restrict__ qh,
           const hf* __restrict__ kh,
           const hf* __restrict__ vth,
           hf* __restrict__ ch)
{
    constexpr int KP = 72, VP = 136;
    constexpr int SKH = 128*KP;
    constexpr int SVH = 64*VP;
    constexpr int STG = SKH + SVH;

    extern __shared__ hf sm[];
    const uint32_t smu = smem_u32(sm);

    const int tid = threadIdx.x, warp = tid >> 5, lane = tid & 31;
    const int g = lane >> 2, t4 = lane & 3;
    const int lr = lane & 7, grp = lane >> 3;
    const int nOffR = lr + ((grp >> 1) << 3), nOffC = (grp & 1) << 3;  // B [n][k]
    const int wm = warp * 16;

    const int z = blockIdx.y;
    const int b = z / HEADS, h = z - b*HEADS;
    const int hc = h * HDIM;
    const int qRow = b*SEQ + blockIdx.x*128;
    const int kvTok0 = b*SEQ;
    const size_t vbase = (size_t)z * HDIM * SEQ;

    uint32_t qf[4][4];
#pragma unroll
    for (int ks = 0; ks < 4; ks++) {
        size_t a0 = (size_t)(qRow + wm + g)*EMBED + hc + ks*16 + t4*2;
        qf[ks][0] = *(const uint32_t*)(qh + a0);
        qf[ks][1] = *(const uint32_t*)(qh + a0 + 8*EMBED);
        qf[ks][2] = *(const uint32_t*)(qh + a0 + 8);
        qf[ks][3] = *(const uint32_t*)(qh + a0 + 8*EMBED + 8);
    }

    float oacc[8][4];
#pragma unroll
    for (int ni = 0; ni < 8; ni++)
#pragma unroll
        for (int j = 0; j < 4; j++) oacc[ni][j] = 0.f;
    float m0 = -1e30f, m1 = -1e30f, l0 = 0.f, l1 = 0.f;

    auto load_stage = [&](int s, int kt) {
        hf* st = sm + s * STG;
        const int kvB = kvTok0 + kt*128;
#pragma unroll
        for (int i = 0; i < 8; i++) {
            int idx = i*256 + tid;
            if (idx < 1024) {                         // K tile: 128 x 64
                int r = idx >> 3, c = idx & 7;
                cp16(st + r*KP + c*8, kh + (size_t)(kvB + r)*EMBED + hc + c*8);
            } else {                                  // V^T tile: 64 x 128
                int j = idx - 1024;
                int r = j >> 4, c = j & 15;
                cp16(st + SKH + r*VP + c*8, vth + vbase + (size_t)r*SEQ + kt*128 + c*8);
            }
        }
    };

    load_stage(0, 0);
    CP_COMMIT();

    for (int kt = 0; kt < SEQ/128; kt++) {
        if (kt + 1 < SEQ/128) { load_stage((kt+1)&1, kt+1); CP_COMMIT(); CP_WAIT(1); }
        else CP_WAIT(0);
        __syncthreads();

        const uint32_t sKu = smu + ((kt & 1) * STG) * 2;
        const uint32_t sVu = sKu + SKH * 2;

        float sacc[16][4];
#pragma unroll
        for (int ni = 0; ni < 16; ni++)
#pragma unroll
            for (int j = 0; j < 4; j++) sacc[ni][j] = 0.f;

#pragma unroll
        for (int ks = 0; ks < 4; ks++) {
#pragma unroll
            for (int p = 0; p < 8; p++) {
                uint32_t r0, r1, r2, r3;
                ldsm4(r0, r1, r2, r3,
                      sKu + (uint32_t)((p*16 + nOffR)*KP + ks*16 + nOffC) * 2);
                uint32_t b0[2] = {r0, r1}, b1[2] = {r2, r3};
                mma16816(sacc[2*p],   qf[ks], b0);
                mma16816(sacc[2*p+1], qf[ks], b1);
            }
        }

        float mt0 = -1e30f, mt1 = -1e30f;
#pragma unroll
        for (int ni = 0; ni < 16; ni++) {
#pragma unroll
            for (int j = 0; j < 4; j++) sacc[ni][j] *= 0.125f;
            mt0 = fmaxf(mt0, fmaxf(sacc[ni][0], sacc[ni][1]));
            mt1 = fmaxf(mt1, fmaxf(sacc[ni][2], sacc[ni][3]));
        }
        mt0 = fmaxf(mt0, __shfl_xor_sync(~0u, mt0, 1));
        mt0 = fmaxf(mt0, __shfl_xor_sync(~0u, mt0, 2));
        mt1 = fmaxf(mt1, __shfl_xor_sync(~0u, mt1, 1));
        mt1 = fmaxf(mt1, __shfl_xor_sync(~0u, mt1, 2));

        const float mn0 = fmaxf(m0, mt0), mn1 = fmaxf(m1, mt1);
        const float sc0 = __expf(m0 - mn0), sc1 = __expf(m1 - mn1);

        float ls0 = 0.f, ls1 = 0.f;
#pragma unroll
        for (int ni = 0; ni < 16; ni++) {
            sacc[ni][0] = __expf(sacc[ni][0] - mn0);
            sacc[ni][1] = __expf(sacc[ni][1] - mn0);
            sacc[ni][2] = __expf(sacc[ni][2] - mn1);
            sacc[ni][3] = __expf(sacc[ni][3] - mn1);
            ls0 += sacc[ni][0] + sacc[ni][1];
            ls1 += sacc[ni][2] + sacc[ni][3];
        }
        ls0 += __shfl_xor_sync(~0u, ls0, 1); ls0 += __shfl_xor_sync(~0u, ls0, 2);
        ls1 += __shfl_xor_sync(~0u, ls1, 1); ls1 += __shfl_xor_sync(~0u, ls1, 2);

        l0 = l0*sc0 + ls0; l1 = l1*sc1 + ls1;
        m0 = mn0; m1 = mn1;
#pragma unroll
        for (int ni = 0; ni < 8; ni++) {
            oacc[ni][0] *= sc0; oacc[ni][1] *= sc0;
            oacc[ni][2] *= sc1; oacc[ni][3] *= sc1;
        }

        uint32_t pf[8][4];
#pragma unroll
        for (int k2 = 0; k2 < 8; k2++) {
            const float* cA = sacc[2*k2];
            const float* cB = sacc[2*k2 + 1];
            pf[k2][0] = pack2(__float2half_rn(cA[0]), __float2half_rn(cA[1]));
            pf[k2][1] = pack2(__float2half_rn(cA[2]), __float2half_rn(cA[3]));
            pf[k2][2] = pack2(__float2half_rn(cB[0]), __float2half_rn(cB[1]));
            pf[k2][3] = pack2(__float2half_rn(cB[2]), __float2half_rn(cB[3]));
        }

#pragma unroll
        for (int k2 = 0; k2 < 8; k2++) {
#pragma unroll
            for (int p = 0; p < 4; p++) {
                uint32_t r0, r1, r2, r3;
                ldsm4(r0, r1, r2, r3,
                      sVu + (uint32_t)((p*16 + nOffR)*VP + k2*16 + nOffC) * 2);
                uint32_t b0[2] = {r0, r1}, b1[2] = {r2, r3};
                mma16816(oacc[2*p],   pf[k2], b0);
                mma16816(oacc[2*p+1], pf[k2], b1);
            }
        }
        __syncthreads();
    }

    const float i0 = 1.f / l0, i1 = 1.f / l1;
#pragma unroll
    for (int ni = 0; ni < 8; ni++) {
        const int col = hc + ni*8 + t4*2;
        const size_t r0 = (size_t)(qRow + wm + g)*EMBED + col;
        const size_t r1 = r0 + 8*EMBED;
        *(uint32_t*)(ch + r0) = pack2(__float2half_rn(oacc[ni][0]*i0),
                                      __float2half_rn(oacc[ni][1]*i0));
        *(uint32_t*)(ch + r1) = pack2(__float2half_rn(oacc[ni][2]*i1),
                                      __float2half_rn(oacc[ni][3]*i1));
    }
}

// ---------------- fp32 -> fp16 ------------------------------------------------
__global__ void __launch_bounds__(256) tohalf_fp32(const float* __restrict__ in,
                                                   hf* __restrict__ oh, int n4)
{
    int i = blockIdx.x*256 + threadIdx.x;
    if (i >= n4) return;
    float4 v = ((const float4*)in)[i];
    uint2 uh;
    uh.x = pack2(__float2half_rn(v.x), __float2half_rn(v.y));
    uh.y = pack2(__float2half_rn(v.z), __float2half_rn(v.w));
    ((uint2*)oh)[i] = uh;
}

// ---------------- bias pack ----------------------------------------------------
__global__ void __launch_bounds__(256)
pack_bias(const float* __restrict__ bq, const float* __restrict__ bk,
          const float* __restrict__ bv, float* __restrict__ dst)
{
    int i = blockIdx.x*256 + threadIdx.x;
    if (i >= 3*EMBED) return;
    dst[i] = (i < EMBED) ? bq[i] : (i < 2*EMBED) ? bk[i - EMBED] : bv[i - 2*EMBED];
}

// ---------------- residual + LayerNorm (optional fp16 out) --------------------
template<bool SPLIT>
__global__ void __launch_bounds__(256)
add_ln(const float* __restrict__ X, const float* __restrict__ Y,
       const float* __restrict__ gamma, const float* __restrict__ beta,
       float* __restrict__ O, hf* __restrict__ Oh)
{
    const size_t base = (size_t)blockIdx.x * EMBED;
    const int tid = threadIdx.x;
    float4 xv = ((const float4*)(X + base))[tid];
    float4 yv = ((const float4*)(Y + base))[tid];
    float4 r; r.x=xv.x+yv.x; r.y=xv.y+yv.y; r.z=xv.z+yv.z; r.w=xv.w+yv.w;

    float s = r.x+r.y+r.z+r.w;
    float sq = r.x*r.x+r.y*r.y+r.z*r.z+r.w*r.w;
    __shared__ float rs[8], rq[8];
#pragma unroll
    for (int o = 16; o > 0; o >>= 1) {
        s += __shfl_xor_sync(~0u, s, o);
        sq += __shfl_xor_sync(~0u, sq, o);
    }
    const int wid = tid>>5, lane = tid&31;
    if (lane == 0) { rs[wid]=s; rq[wid]=sq; }
    __syncthreads();
    s = rs[0]; sq = rq[0];
#pragma unroll
    for (int w = 1; w < 8; w++) { s += rs[w]; sq += rq[w]; }

    const float mu = s * (1.f/EMBED);
    const float var = sq * (1.f/EMBED) - mu*mu;
    const float rstd = rsqrtf(var + 1e-6f);
    float4 g = ((const float4*)gamma)[tid];
    float4 bb = ((const float4*)beta)[tid];
    float4 o;
    o.x=(r.x-mu)*rstd*g.x+bb.x; o.y=(r.y-mu)*rstd*g.y+bb.y;
    o.z=(r.z-mu)*rstd*g.z+bb.z; o.w=(r.w-mu)*rstd*g.w+bb.w;
    ((float4*)(O + base))[tid] = o;
    if (SPLIT) {
        uint2 uh;
        uh.x = pack2(__float2half_rn(o.x), __float2half_rn(o.y));
        uh.y = pack2(__float2half_rn(o.z), __float2half_rn(o.w));
        ((uint2*)(Oh + base))[tid] = uh;
    }
}

// ---------------- host --------------------------------------------------------
extern "C" void kernel_launch(void* const* d_in, const int* in_sizes, int n_in,
                              void* d_out, int out_size)
{
    const float* x  = (const float*)d_in[0];
    const float* Wq = (const float*)d_in[1];  const float* bq = (const float*)d_in[2];
    const float* Wk = (const float*)d_in[3];  const float* bk = (const float*)d_in[4];
    const float* Wv = (const float*)d_in[5];  const float* bv = (const float*)d_in[6];
    const float* Wo = (const float*)d_in[7];  const float* bo = (const float*)d_in[8];
    const float* g1 = (const float*)d_in[9];  const float* be1 = (const float*)d_in[10];
    const float* W1 = (const float*)d_in[11]; const float* b1 = (const float*)d_in[12];
    const float* W2 = (const float*)d_in[13]; const float* b2 = (const float*)d_in[14];
    const float* g2 = (const float*)d_in[15]; const float* be2 = (const float*)d_in[16];
    float* out = (float*)d_out;

    float *tmp, *x1, *bqkv;
    hf *xh,*qh,*kh,*vth,*ch,*x1h,*hh,*w16;
    cudaGetSymbolAddress((void**)&tmp,  g_tmp);
    cudaGetSymbolAddress((void**)&x1,   g_x1);
    cudaGetSymbolAddress((void**)&bqkv, g_bqkv);
    cudaGetSymbolAddress((void**)&xh,   g_x_hi);
    cudaGetSymbolAddress((void**)&qh,   g_q_hi);
    cudaGetSymbolAddress((void**)&kh,   g_k_hi);
    cudaGetSymbolAddress((void**)&vth,  g_vt_hi);
    cudaGetSymbolAddress((void**)&ch,   g_c_hi);
    cudaGetSymbolAddress((void**)&x1h,  g_x1_hi);
    cudaGetSymbolAddress((void**)&hh,   g_h_hi);
    cudaGetSymbolAddress((void**)&w16,  g_w16);

    constexpr int SMB  = 2 * (128*40 + 32*136) * 2;   // 37888 B
    constexpr int FASM = (128*72 + 64*136) * 2 * 2;   // 71680 B
    cudaFuncSetAttribute(bgemm<128,0>, cudaFuncAttributeMaxDynamicSharedMemorySize, SMB);
    cudaFuncSetAttribute(bgemm<128,2>, cudaFuncAttributeMaxDynamicSharedMemorySize, SMB);
    cudaFuncSetAttribute(bgemm<128,3>, cudaFuncAttributeMaxDynamicSharedMemorySize, SMB);
    cudaFuncSetAttribute(flash_attn,   cudaFuncAttributeMaxDynamicSharedMemorySize, FASM);

    // prep: fp32 -> fp16, original layouts (no transposes needed)
    tohalf_fp32<<<NTOK*EMBED/4/256, 256>>>(x, xh, NTOK*EMBED/4);
    tohalf_fp32<<<1024, 256>>>(Wq, w16+OFF_WQ, 1024*1024/4);
    tohalf_fp32<<<1024, 256>>>(Wk, w16+OFF_WK, 1024*1024/4);
    tohalf_fp32<<<1024, 256>>>(Wv, w16+OFF_WV, 1024*1024/4);
    tohalf_fp32<<<1024, 256>>>(Wo, w16+OFF_WO, 1024*1024/4);
    tohalf_fp32<<<4096, 256>>>(W1, w16+OFF_W1, 4096*1024/4);
    tohalf_fp32<<<4096, 256>>>(W2, w16+OFF_W2, 4096*1024/4);
    pack_bias<<<12, 256>>>(bq, bk, bv, bqkv);

    // fused QKV: N=3072; q,k row-major fp16; v written transposed per head
    bgemm<128,3><<<dim3(24,32), 256, SMB>>>(xh, EMBED, w16, EMBED,
                                            nullptr, qh, kh, vth, EMBED,
                                            bqkv, 1.f, EMBED);

    // fused attention -> ctx (fp16)
    flash_attn<<<dim3(SEQ/128, NBH), 256, FASM>>>(qh, kh, vth, ch);

    // attn_out = ctx @ Wo + bo (fp32)
    bgemm<128,0><<<dim3(8,32), 256, SMB>>>(ch, EMBED, w16+OFF_WO, EMBED,
                                           tmp, nullptr, nullptr, nullptr, EMBED,
                                           bo, 1.f, EMBED);

    add_ln<true><<<NTOK, 256>>>(x, tmp, g1, be1, x1, x1h);

    // h = relu(x1 @ W1 + b1): fp16
    bgemm<128,2><<<dim3(32,32), 256, SMB>>>(x1h, EMBED, w16+OFF_W1, HIDDEN,
                                            nullptr, hh, nullptr, nullptr, HIDDEN,
                                            b1, 1.f, EMBED);

    // f2 = h @ W2 + b2 (fp32)
    bgemm<128,0><<<dim3(8,32), 256, SMB>>>(hh, HIDDEN, w16+OFF_W2, EMBED,
                                           tmp, nullptr, nullptr, nullptr, EMBED,
                                           b2, 1.f, HIDDEN);

    add_ln<false><<<NTOK, 256>>>(x1, tmp, g2, be2, out, nullptr);
}

// round 9
// speedup vs baseline: 8.8332x; 1.0498x over previous
#include <cuda_runtime.h>
#include <cuda_fp16.h>
#include <cstdint>

#define EMBED  1024
#define HEADS  16
#define HDIM   64
#define HIDDEN 4096
#define SEQ    2048
#define BATCH  2
#define NTOK   (BATCH*SEQ)
#define NBH    (BATCH*HEADS)

typedef __half hf;

// ---------------- static scratch --------------------------------------------
__device__ hf    g_x_hi[NTOK*EMBED];
__device__ hf    g_q_hi[NTOK*EMBED];
__device__ hf    g_k_hi[NTOK*EMBED];
__device__ hf    g_vt_hi[NTOK*EMBED];                 // [b,h][64][2048]
__device__ hf    g_c_hi[NTOK*EMBED];
__device__ float g_tmp[NTOK*EMBED];
__device__ float g_x1[NTOK*EMBED];
__device__ hf    g_x1_hi[NTOK*EMBED];
__device__ hf    g_h_hi[(size_t)NTOK*HIDDEN];
__device__ hf    g_w16[12*1024*1024];                 // fp16 weights, ORIGINAL [k][n] layout
__device__ float g_bqkv[3*EMBED];
#define OFF_WQ 0
#define OFF_WK (1*1024*1024)
#define OFF_WV (2*1024*1024)
#define OFF_WO (3*1024*1024)
#define OFF_W1 (4*1024*1024)
#define OFF_W2 (8*1024*1024)

// ---------------- helpers ----------------------------------------------------
__device__ __forceinline__ uint32_t smem_u32(const void* p) {
    uint32_t a;
    asm("{ .reg .u64 t; cvta.to.shared.u64 t, %1; cvt.u32.u64 %0, t; }" : "=r"(a) : "l"(p));
    return a;
}
__device__ __forceinline__ void cp16(const void* smem_dst, const void* gsrc) {
    uint32_t d = smem_u32(smem_dst);
    asm volatile("cp.async.cg.shared.global [%0], [%1], 16;" :: "r"(d), "l"(gsrc) : "memory");
}
#define CP_COMMIT() asm volatile("cp.async.commit_group;" ::: "memory")
#define CP_WAIT(n)  asm volatile("cp.async.wait_group %0;" :: "n"(n) : "memory")

__device__ __forceinline__ void mma16816(float* c, const uint32_t* a, const uint32_t* b) {
    asm volatile("mma.sync.aligned.m16n8k16.row.col.f32.f16.f16.f32 "
        "{%0,%1,%2,%3}, {%4,%5,%6,%7}, {%8,%9}, {%0,%1,%2,%3};"
        : "+f"(c[0]), "+f"(c[1]), "+f"(c[2]), "+f"(c[3])
        : "r"(a[0]), "r"(a[1]), "r"(a[2]), "r"(a[3]), "r"(b[0]), "r"(b[1]));
}
__device__ __forceinline__ void ldsm4(uint32_t& r0, uint32_t& r1, uint32_t& r2,
                                      uint32_t& r3, uint32_t a) {
    asm volatile("ldmatrix.sync.aligned.m8n8.x4.shared.b16 {%0,%1,%2,%3}, [%4];"
        : "=r"(r0), "=r"(r1), "=r"(r2), "=r"(r3) : "r"(a));
}
__device__ __forceinline__ void ldsm4t(uint32_t& r0, uint32_t& r1, uint32_t& r2,
                                       uint32_t& r3, uint32_t a) {
    asm volatile("ldmatrix.sync.aligned.m8n8.x4.trans.shared.b16 {%0,%1,%2,%3}, [%4];"
        : "=r"(r0), "=r"(r1), "=r"(r2), "=r"(r3) : "r"(a));
}
__device__ __forceinline__ uint32_t pack2(hf a, hf b) {
    __half2 t; t.x = a; t.y = b; return *(uint32_t*)&t;
}

// ---------------- fp16 HMMA GEMM, weights untransposed [k][n] -----------------
// D[M,N] = alpha*(A[m,k] @ B[k,n]) (+bias)(+epi). BM=128, BK=64, 2 stages.
// EPI: 0 = fp32 out; 2 = relu + fp16 out; 3 = fused QKV epilogue
template<int BN, int EPI>
__global__ void __launch_bounds__(256, 2)
bgemm(const hf* __restrict__ Ah, int lda,
      const hf* __restrict__ Bh, int ldb,
      float* __restrict__ Cf, hf* __restrict__ Ch,
      hf* __restrict__ Kp, hf* __restrict__ Vt, int ldc,
      const float* __restrict__ bias, float alpha, int K)
{
    constexpr int BM = 128, BK = 64, BKP = 72, BNP = BN + 8;
    constexpr int WM = 2, WN = 4;
    constexpr int WTM = BM / WM, WTN = BN / WN;       // 64 x 32
    constexpr int MI = WTM / 16, NI = WTN / 8;        // 4, 4
    constexpr int ASZ = BM * BKP;                     // 9216
    constexpr int BSZ = BK * BNP;                     // 8704
    constexpr int SST = ASZ + BSZ;                    // 17920

    extern __shared__ hf sm[];
    const uint32_t smu = smem_u32(sm);

    const int tid = threadIdx.x;
    const int warp = tid >> 5, lane = tid & 31;
    const int g = lane >> 2, t4 = lane & 3;
    const int lr = lane & 7, grp = lane >> 3;
    const int aOffR = lr + ((grp & 1) << 3), aOffC = (grp >> 1) << 3;  // A [m][k]
    const int tOffR = lr + ((grp & 1) << 3), tOffC = (grp >> 1) << 3;  // B trans [k][n]
    const int wm = (warp % WM) * WTM;
    const int wn = (warp / WM) * WTN;

    const int rowBase = blockIdx.y * BM;
    const int colBase = blockIdx.x * BN;
    const int seg   = colBase >> 10;                  // EPI3 only
    const int lcol0 = colBase & 1023;

    const hf* Bbase = (EPI == 3)
        ? Bh + (size_t)seg * (1024*1024) + lcol0
        : Bh + colBase;

    float acc[MI][NI][4];
#pragma unroll
    for (int mi = 0; mi < MI; mi++)
#pragma unroll
        for (int ni = 0; ni < NI; ni++)
#pragma unroll
            for (int i = 0; i < 4; i++) acc[mi][ni][i] = 0.f;

    auto load_stage = [&](int s, int k0) {
        hf* st = sm + s * SST;
#pragma unroll
        for (int i = 0; i < 8; i++) {
            int idx = i * 256 + tid;
            if (idx < 1024) {                         // A: 128 rows x 8 chunks
                int r = idx >> 3, c = idx & 7;
                cp16(st + r*BKP + c*8, Ah + (size_t)(rowBase + r)*lda + k0 + c*8);
            } else {                                  // B: 64 k-rows x 16 chunks
                int j = idx - 1024;
                int r = j >> 4, c = j & 15;
                cp16(st + ASZ + r*BNP + c*8, Bbase + (size_t)(k0 + r)*ldb + c*8);
            }
        }
    };

    const int T = K / BK;
    load_stage(0, 0);
    CP_COMMIT();

    for (int t = 0; t < T; t++) {
        if (t + 1 < T) {
            load_stage((t + 1) & 1, (t + 1) * BK);
            CP_COMMIT();
            CP_WAIT(1);
        } else {
            CP_WAIT(0);
        }
        __syncthreads();

        const uint32_t sAu = smu + ((t & 1) * SST) * 2;
        const uint32_t sBu = sAu + ASZ * 2;

#pragma unroll
        for (int kk = 0; kk < BK; kk += 16) {
            uint32_t ah[MI][4];
#pragma unroll
            for (int mi = 0; mi < MI; mi++)
                ldsm4(ah[mi][0], ah[mi][1], ah[mi][2], ah[mi][3],
                      sAu + (uint32_t)((wm + mi*16 + aOffR)*BKP + kk + aOffC) * 2);
            uint32_t bh[NI][2];
#pragma unroll
            for (int p = 0; p < NI/2; p++)
                ldsm4t(bh[2*p][0], bh[2*p][1], bh[2*p+1][0], bh[2*p+1][1],
                       sBu + (uint32_t)((kk + tOffR)*BNP + wn + p*16 + tOffC) * 2);
#pragma unroll
            for (int mi = 0; mi < MI; mi++)
#pragma unroll
                for (int ni = 0; ni < NI; ni++)
                    mma16816(acc[mi][ni], ah[mi], bh[ni]);
        }
        __syncthreads();
    }

    // ---- epilogue ------------------------------------------------------------
#pragma unroll
    for (int ni = 0; ni < NI; ni++) {
        int colW = wn + ni*8 + t4*2;
        int gcol = colBase + colW;
        float b0 = 0.f, b1 = 0.f;
        if (bias) { b0 = __ldg(bias + gcol); b1 = __ldg(bias + gcol + 1); }
#pragma unroll
        for (int mi = 0; mi < MI; mi++) {
            int row0 = rowBase + wm + mi*16 + g;
            float v0 = acc[mi][ni][0] * alpha + b0;
            float v1 = acc[mi][ni][1] * alpha + b1;
            float v2 = acc[mi][ni][2] * alpha + b0;
            float v3 = acc[mi][ni][3] * alpha + b1;
            if (EPI == 2) {
                v0 = fmaxf(v0, 0.f); v1 = fmaxf(v1, 0.f);
                v2 = fmaxf(v2, 0.f); v3 = fmaxf(v3, 0.f);
            }
            if (EPI == 0) {
                float2 r01; r01.x = v0; r01.y = v1;
                float2 r23; r23.x = v2; r23.y = v3;
                *(float2*)(Cf + (size_t)row0     * ldc + gcol) = r01;
                *(float2*)(Cf + (size_t)(row0+8) * ldc + gcol) = r23;
            } else if (EPI == 2) {
                *(uint32_t*)(Ch + (size_t)row0     * ldc + gcol) =
                    pack2(__float2half_rn(v0), __float2half_rn(v1));
                *(uint32_t*)(Ch + (size_t)(row0+8) * ldc + gcol) =
                    pack2(__float2half_rn(v2), __float2half_rn(v3));
            } else {                                  // EPI 3: fused QKV
                int lcol = lcol0 + colW;
                if (seg < 2) {
                    hf* dst = seg ? Kp : Ch;
                    *(uint32_t*)(dst + (size_t)row0     * EMBED + lcol) =
                        pack2(__float2half_rn(v0), __float2half_rn(v1));
                    *(uint32_t*)(dst + (size_t)(row0+8) * EMBED + lcol) =
                        pack2(__float2half_rn(v2), __float2half_rn(v3));
                } else {                              // V -> [b,h][64][2048]
                    int head = lcol >> 6, d = lcol & 63;
                    int bb0 = row0 >> 11, t0 = row0 & 2047;
                    int bb1 = (row0+8) >> 11, t1 = (row0+8) & 2047;
                    size_t base0 = ((size_t)(bb0*HEADS + head)*64 + d)*2048;
                    size_t base1 = ((size_t)(bb1*HEADS + head)*64 + d)*2048;
                    Vt[base0 + t0]        = __float2half_rn(v0);
                    Vt[base0 + 2048 + t0] = __float2half_rn(v1);
                    Vt[base1 + t1]        = __float2half_rn(v2);
                    Vt[base1 + 2048 + t1] = __float2half_rn(v3);
                }
            }
        }
    }
}

// ---------------- fused flash attention (fp16, ldmatrix) ----------------------
__global__ void __launch_bounds__(256)
flash_attn(const hf* __restrict__ qh,
           const hf* __restrict__ kh,
           const hf* __restrict__ vth,
           hf* __restrict__ ch)
{
    constexpr int KP = 72, VP = 136;
    constexpr int SKH = 128*KP;
    constexpr int SVH = 64*VP;
    constexpr int STG = SKH + SVH;

    extern __shared__ hf sm[];
    const uint32_t smu = smem_u32(sm);

    const int tid = threadIdx.x, warp = tid >> 5, lane = tid & 31;
    const int g = lane >> 2, t4 = lane & 3;
    const int lr = lane & 7, grp = lane >> 3;
    const int nOffR = lr + ((grp >> 1) << 3), nOffC = (grp & 1) << 3;  // B [n][k]
    const int wm = warp * 16;

    const int z = blockIdx.y;
    const int b = z / HEADS, h = z - b*HEADS;
    const int hc = h * HDIM;
    const int qRow = b*SEQ + blockIdx.x*128;
    const int kvTok0 = b*SEQ;
    const size_t vbase = (size_t)z * HDIM * SEQ;

    uint32_t qf[4][4];
#pragma unroll
    for (int ks = 0; ks < 4; ks++) {
        size_t a0 = (size_t)(qRow + wm + g)*EMBED + hc + ks*16 + t4*2;
        qf[ks][0] = *(const uint32_t*)(qh + a0);
        qf[ks][1] = *(const uint32_t*)(qh + a0 + 8*EMBED);
        qf[ks][2] = *(const uint32_t*)(qh + a0 + 8);
        qf[ks][3] = *(const uint32_t*)(qh + a0 + 8*EMBED + 8);
    }

    float oacc[8][4];
#pragma unroll
    for (int ni = 0; ni < 8; ni++)
#pragma unroll
        for (int j = 0; j < 4; j++) oacc[ni][j] = 0.f;
    float m0 = -1e30f, m1 = -1e30f, l0 = 0.f, l1 = 0.f;

    auto load_stage = [&](int s, int kt) {
        hf* st = sm + s * STG;
        const int kvB = kvTok0 + kt*128;
#pragma unroll
        for (int i = 0; i < 8; i++) {
            int idx = i*256 + tid;
            if (idx < 1024) {                         // K tile: 128 x 64
                int r = idx >> 3, c = idx & 7;
                cp16(st + r*KP + c*8, kh + (size_t)(kvB + r)*EMBED + hc + c*8);
            } else {                                  // V^T tile: 64 x 128
                int j = idx - 1024;
                int r = j >> 4, c = j & 15;
                cp16(st + SKH + r*VP + c*8, vth + vbase + (size_t)r*SEQ + kt*128 + c*8);
            }
        }
    };

    load_stage(0, 0);
    CP_COMMIT();

    for (int kt = 0; kt < SEQ/128; kt++) {
        if (kt + 1 < SEQ/128) { load_stage((kt+1)&1, kt+1); CP_COMMIT(); CP_WAIT(1); }
        else CP_WAIT(0);
        __syncthreads();

        const uint32_t sKu = smu + ((kt & 1) * STG) * 2;
        const uint32_t sVu = sKu + SKH * 2;

        float sacc[16][4];
#pragma unroll
        for (int ni = 0; ni < 16; ni++)
#pragma unroll
            for (int j = 0; j < 4; j++) sacc[ni][j] = 0.f;

#pragma unroll
        for (int ks = 0; ks < 4; ks++) {
#pragma unroll
            for (int p = 0; p < 8; p++) {
                uint32_t r0, r1, r2, r3;
                ldsm4(r0, r1, r2, r3,
                      sKu + (uint32_t)((p*16 + nOffR)*KP + ks*16 + nOffC) * 2);
                uint32_t b0[2] = {r0, r1}, b1[2] = {r2, r3};
                mma16816(sacc[2*p],   qf[ks], b0);
                mma16816(sacc[2*p+1], qf[ks], b1);
            }
        }

        float mt0 = -1e30f, mt1 = -1e30f;
#pragma unroll
        for (int ni = 0; ni < 16; ni++) {
#pragma unroll
            for (int j = 0; j < 4; j++) sacc[ni][j] *= 0.125f;
            mt0 = fmaxf(mt0, fmaxf(sacc[ni][0], sacc[ni][1]));
            mt1 = fmaxf(mt1, fmaxf(sacc[ni][2], sacc[ni][3]));
        }
        mt0 = fmaxf(mt0, __shfl_xor_sync(~0u, mt0, 1));
        mt0 = fmaxf(mt0, __shfl_xor_sync(~0u, mt0, 2));
        mt1 = fmaxf(mt1, __shfl_xor_sync(~0u, mt1, 1));
        mt1 = fmaxf(mt1, __shfl_xor_sync(~0u, mt1, 2));

        const float mn0 = fmaxf(m0, mt0), mn1 = fmaxf(m1, mt1);
        const float sc0 = __expf(m0 - mn0), sc1 = __expf(m1 - mn1);

        float ls0 = 0.f, ls1 = 0.f;
#pragma unroll
        for (int ni = 0; ni < 16; ni++) {
            sacc[ni][0] = __expf(sacc[ni][0] - mn0);
            sacc[ni][1] = __expf(sacc[ni][1] - mn0);
            sacc[ni][2] = __expf(sacc[ni][2] - mn1);
            sacc[ni][3] = __expf(sacc[ni][3] - mn1);
            ls0 += sacc[ni][0] + sacc[ni][1];
            ls1 += sacc[ni][2] + sacc[ni][3];
        }
        ls0 += __shfl_xor_sync(~0u, ls0, 1); ls0 += __shfl_xor_sync(~0u, ls0, 2);
        ls1 += __shfl_xor_sync(~0u, ls1, 1); ls1 += __shfl_xor_sync(~0u, ls1, 2);

        l0 = l0*sc0 + ls0; l1 = l1*sc1 + ls1;
        m0 = mn0; m1 = mn1;
#pragma unroll
        for (int ni = 0; ni < 8; ni++) {
            oacc[ni][0] *= sc0; oacc[ni][1] *= sc0;
            oacc[ni][2] *= sc1; oacc[ni][3] *= sc1;
        }

        uint32_t pf[8][4];
#pragma unroll
        for (int k2 = 0; k2 < 8; k2++) {
            const float* cA = sacc[2*k2];
            const float* cB = sacc[2*k2 + 1];
            pf[k2][0] = pack2(__float2half_rn(cA[0]), __float2half_rn(cA[1]));
            pf[k2][1] = pack2(__float2half_rn(cA[2]), __float2half_rn(cA[3]));
            pf[k2][2] = pack2(__float2half_rn(cB[0]), __float2half_rn(cB[1]));
            pf[k2][3] = pack2(__float2half_rn(cB[2]), __float2half_rn(cB[3]));
        }

#pragma unroll
        for (int k2 = 0; k2 < 8; k2++) {
#pragma unroll
            for (int p = 0; p < 4; p++) {
                uint32_t r0, r1, r2, r3;
                ldsm4(r0, r1, r2, r3,
                      sVu + (uint32_t)((p*16 + nOffR)*VP + k2*16 + nOffC) * 2);
                uint32_t b0[2] = {r0, r1}, b1[2] = {r2, r3};
                mma16816(oacc[2*p],   pf[k2], b0);
                mma16816(oacc[2*p+1], pf[k2], b1);
            }
        }
        __syncthreads();
    }

    const float i0 = 1.f / l0, i1 = 1.f / l1;
#pragma unroll
    for (int ni = 0; ni < 8; ni++) {
        const int col = hc + ni*8 + t4*2;
        const size_t r0 = (size_t)(qRow + wm + g)*EMBED + col;
        const size_t r1 = r0 + 8*EMBED;
        *(uint32_t*)(ch + r0) = pack2(__float2half_rn(oacc[ni][0]*i0),
                                      __float2half_rn(oacc[ni][1]*i0));
        *(uint32_t*)(ch + r1) = pack2(__float2half_rn(oacc[ni][2]*i1),
                                      __float2half_rn(oacc[ni][3]*i1));
    }
}

// ---------------- fused prep: all weights + x -> fp16, bias pack ---------------
__global__ void __launch_bounds__(256)
prep_all(const float* __restrict__ Wq, const float* __restrict__ Wk,
         const float* __restrict__ Wv, const float* __restrict__ Wo,
         const float* __restrict__ W1, const float* __restrict__ W2,
         const float* __restrict__ x,
         const float* __restrict__ bq, const float* __restrict__ bk,
         const float* __restrict__ bv,
         hf* __restrict__ w16, hf* __restrict__ xh, float* __restrict__ bqkv)
{
    const int c = blockIdx.x*256 + threadIdx.x;       // float4 chunk index
    constexpr int SMALL = 262144;                     // chunks per 1M-elem weight
    constexpr int C_SM  = 4*SMALL;                    // 1048576
    constexpr int C_W1  = C_SM + 1048576;
    constexpr int C_W2  = C_W1 + 1048576;
    constexpr int C_X   = C_W2 + 1048576;

    const float* src;
    hf* dst;
    int off;
    if (c < C_SM) {
        int seg = c >> 18;
        src = (seg == 0) ? Wq : (seg == 1) ? Wk : (seg == 2) ? Wv : Wo;
        off = c & (SMALL - 1);
        dst = w16 + (size_t)seg * 1048576;
    } else if (c < C_W1) {
        src = W1; off = c - C_SM;  dst = w16 + OFF_W1;
    } else if (c < C_W2) {
        src = W2; off = c - C_W1;  dst = w16 + OFF_W2;
    } else if (c < C_X) {
        src = x;  off = c - C_W2;  dst = xh;
    } else {
        int off2 = c - C_X;                            // bias: 768 chunks
        if (off2 < 768) {
            float4 v = (off2 < 256) ? ((const float4*)bq)[off2]
                     : (off2 < 512) ? ((const float4*)bk)[off2 - 256]
                                    : ((const float4*)bv)[off2 - 512];
            ((float4*)bqkv)[off2] = v;
        }
        return;
    }
    float4 v = ((const float4*)src)[off];
    uint2 uh;
    uh.x = pack2(__float2half_rn(v.x), __float2half_rn(v.y));
    uh.y = pack2(__float2half_rn(v.z), __float2half_rn(v.w));
    ((uint2*)dst)[off] = uh;
}

// ---------------- residual + LayerNorm (optional fp16 out) --------------------
template<bool SPLIT>
__global__ void __launch_bounds__(256)
add_ln(const float* __restrict__ X, const float* __restrict__ Y,
       const float* __restrict__ gamma, const float* __restrict__ beta,
       float* __restrict__ O, hf* __restrict__ Oh)
{
    const size_t base = (size_t)blockIdx.x * EMBED;
    const int tid = threadIdx.x;
    float4 xv = ((const float4*)(X + base))[tid];
    float4 yv = ((const float4*)(Y + base))[tid];
    float4 r; r.x=xv.x+yv.x; r.y=xv.y+yv.y; r.z=xv.z+yv.z; r.w=xv.w+yv.w;

    float s = r.x+r.y+r.z+r.w;
    float sq = r.x*r.x+r.y*r.y+r.z*r.z+r.w*r.w;
    __shared__ float rs[8], rq[8];
#pragma unroll
    for (int o = 16; o > 0; o >>= 1) {
        s += __shfl_xor_sync(~0u, s, o);
        sq += __shfl_xor_sync(~0u, sq, o);
    }
    const int wid = tid>>5, lane = tid&31;
    if (lane == 0) { rs[wid]=s; rq[wid]=sq; }
    __syncthreads();
    s = rs[0]; sq = rq[0];
#pragma unroll
    for (int w = 1; w < 8; w++) { s += rs[w]; sq += rq[w]; }

    const float mu = s * (1.f/EMBED);
    const float var = sq * (1.f/EMBED) - mu*mu;
    const float rstd = rsqrtf(var + 1e-6f);
    float4 g = ((const float4*)gamma)[tid];
    float4 bb = ((const float4*)beta)[tid];
    float4 o;
    o.x=(r.x-mu)*rstd*g.x+bb.x; o.y=(r.y-mu)*rstd*g.y+bb.y;
    o.z=(r.z-mu)*rstd*g.z+bb.z; o.w=(r.w-mu)*rstd*g.w+bb.w;
    ((float4*)(O + base))[tid] = o;
    if (SPLIT) {
        uint2 uh;
        uh.x = pack2(__float2half_rn(o.x), __float2half_rn(o.y));
        uh.y = pack2(__float2half_rn(o.z), __float2half_rn(o.w));
        ((uint2*)(Oh + base))[tid] = uh;
    }
}

// ---------------- host --------------------------------------------------------
extern "C" void kernel_launch(void* const* d_in, const int* in_sizes, int n_in,
                              void* d_out, int out_size)
{
    const float* x  = (const float*)d_in[0];
    const float* Wq = (const float*)d_in[1];  const float* bq = (const float*)d_in[2];
    const float* Wk = (const float*)d_in[3];  const float* bk = (const float*)d_in[4];
    const float* Wv = (const float*)d_in[5];  const float* bv = (const float*)d_in[6];
    const float* Wo = (const float*)d_in[7];  const float* bo = (const float*)d_in[8];
    const float* g1 = (const float*)d_in[9];  const float* be1 = (const float*)d_in[10];
    const float* W1 = (const float*)d_in[11]; const float* b1 = (const float*)d_in[12];
    const float* W2 = (const float*)d_in[13]; const float* b2 = (const float*)d_in[14];
    const float* g2 = (const float*)d_in[15]; const float* be2 = (const float*)d_in[16];
    float* out = (float*)d_out;

    float *tmp, *x1, *bqkv;
    hf *xh,*qh,*kh,*vth,*ch,*x1h,*hh,*w16;
    cudaGetSymbolAddress((void**)&tmp,  g_tmp);
    cudaGetSymbolAddress((void**)&x1,   g_x1);
    cudaGetSymbolAddress((void**)&bqkv, g_bqkv);
    cudaGetSymbolAddress((void**)&xh,   g_x_hi);
    cudaGetSymbolAddress((void**)&qh,   g_q_hi);
    cudaGetSymbolAddress((void**)&kh,   g_k_hi);
    cudaGetSymbolAddress((void**)&vth,  g_vt_hi);
    cudaGetSymbolAddress((void**)&ch,   g_c_hi);
    cudaGetSymbolAddress((void**)&x1h,  g_x1_hi);
    cudaGetSymbolAddress((void**)&hh,   g_h_hi);
    cudaGetSymbolAddress((void**)&w16,  g_w16);

    constexpr int SMB  = 2 * (128*72 + 64*136) * 2;   // 71680 B
    constexpr int FASM = (128*72 + 64*136) * 2 * 2;   // 71680 B
    cudaFuncSetAttribute(bgemm<128,0>, cudaFuncAttributeMaxDynamicSharedMemorySize, SMB);
    cudaFuncSetAttribute(bgemm<128,2>, cudaFuncAttributeMaxDynamicSharedMemorySize, SMB);
    cudaFuncSetAttribute(bgemm<128,3>, cudaFuncAttributeMaxDynamicSharedMemorySize, SMB);
    cudaFuncSetAttribute(flash_attn,   cudaFuncAttributeMaxDynamicSharedMemorySize, FASM);

    // single fused prep: 6 weights + x -> fp16, bias pack
    // chunks: 4*262144 + 2*1048576 + 1048576 + 768 = 4195840 -> ceil/256
    prep_all<<<(4195840 + 255)/256, 256>>>(Wq, Wk, Wv, Wo, W1, W2, x,
                                           bq, bk, bv, w16, xh, bqkv);

    // fused QKV: N=3072; q,k row-major fp16; v written transposed per head
    bgemm<128,3><<<dim3(24,32), 256, SMB>>>(xh, EMBED, w16, EMBED,
                                            nullptr, qh, kh, vth, EMBED,
                                            bqkv, 1.f, EMBED);

    // fused attention -> ctx (fp16)
    flash_attn<<<dim3(SEQ/128, NBH), 256, FASM>>>(qh, kh, vth, ch);

    // attn_out = ctx @ Wo + bo (fp32)
    bgemm<128,0><<<dim3(8,32), 256, SMB>>>(ch, EMBED, w16+OFF_WO, EMBED,
                                           tmp, nullptr, nullptr, nullptr, EMBED,
                                           bo, 1.f, EMBED);

    add_ln<true><<<NTOK, 256>>>(x, tmp, g1, be1, x1, x1h);

    // h = relu(x1 @ W1 + b1): fp16
    bgemm<128,2><<<dim3(32,32), 256, SMB>>>(x1h, EMBED, w16+OFF_W1, HIDDEN,
                                            nullptr, hh, nullptr, nullptr, HIDDEN,
                                            b1, 1.f, EMBED);

    // f2 = h @ W2 + b2 (fp32)
    bgemm<128,0><<<dim3(8,32), 256, SMB>>>(hh, HIDDEN, w16+OFF_W2, EMBED,
                                           tmp, nullptr, nullptr, nullptr, EMBED,
                                           b2, 1.f, HIDDEN);

    add_ln<false><<<NTOK, 256>>>(x1, tmp, g2, be2, out, nullptr);
}